// round 7
// baseline (speedup 1.0000x reference)
#include <cuda_runtime.h>
#include <cuda_fp16.h>
#include <cstdint>

// Problem constants
#define B_ 8
#define W_ 5
#define S_ 5
#define C_ 640
#define HW_ 100
#define Q_ 75
#define NK_ 5

#define MT_ 59            // M-tiles of 128 over 7500 rows (padded to 7552)
#define MROWS_ 7500
#define K16_ 40           // K steps of 16 (C=640)

// ---------------------------------------------------------------------------
// Scratch (zero-init; pad regions never written -> zeros).
// A: [b][mt][k16][mg(8)] 16x16 fp16 tiles in m16n8k16 A-fragment order
//    (scaled by qd_inv).
// B: [bw][k16][n16(32)] paired 16x8 fp16 tiles (scaled by sup_inv).
// ---------------------------------------------------------------------------
__device__ uint32_t g_A[B_ * MT_ * K16_ * 8 * 128];    // 77.3 MB
__device__ uint32_t g_Bm[B_ * W_ * K16_ * 32 * 128];   // 26.2 MB
__device__ float g_rowsum[B_ * W_ * MROWS_];
__device__ float g_sup_inv[B_ * W_ * C_];
__device__ float g_proto[B_ * W_ * C_];
__device__ float g_pn[B_ * W_ * C_];
__device__ float g_qn[B_ * Q_ * C_];

__device__ __forceinline__ float warpSum(float v) {
    #pragma unroll
    for (int o = 16; o; o >>= 1) v += __shfl_xor_sync(0xffffffffu, v, o);
    return v;
}

// fp16-accumulate HMMA
__device__ __forceinline__ void mma16h(uint32_t* d, uint4 a, uint32_t b0, uint32_t b1) {
    asm volatile(
        "mma.sync.aligned.m16n8k16.row.col.f16.f16.f16.f16 "
        "{%0,%1}, {%2,%3,%4,%5}, {%6,%7}, {%0,%1};"
        : "+r"(d[0]), "+r"(d[1])
        : "r"(a.x), "r"(a.y), "r"(a.z), "r"(a.w), "r"(b0), "r"(b1));
}

__device__ __forceinline__ void ins5(float (&t)[5], float v) {
    if (v > t[0]) {
        t[0] = v;
        if (t[0] > t[1]) { float x = t[1]; t[1] = t[0]; t[0] = x;
            if (t[1] > t[2]) { x = t[2]; t[2] = t[1]; t[1] = x;
                if (t[2] > t[3]) { x = t[3]; t[3] = t[2]; t[2] = x;
                    if (t[3] > t[4]) { x = t[4]; t[4] = t[3]; t[3] = x; } } } }
    }
}

__device__ __forceinline__ uint32_t pack_h2(float v0, float v1) {
    __half2 h = __floats2half2_rn(v0, v1);   // .x (low) = v0
    return *(uint32_t*)&h;
}

__device__ __forceinline__ uint32_t smem_u32p(const void* p) {
    uint32_t a;
    asm("{ .reg .u64 t; cvta.to.shared.u64 t, %1; cvt.u32.u64 %0, t; }" : "=r"(a) : "l"(p));
    return a;
}

__device__ __forceinline__ void cpasync16(uint32_t dst, const void* src) {
    asm volatile("cp.async.cg.shared.global [%0], [%1], 16;" :: "r"(dst), "l"(src));
}

// ---------------------------------------------------------------------------
// Kernel 1: per-(bw,c) support sums. One warp per (bw,c). grid=3200, block=256.
// ---------------------------------------------------------------------------
__global__ void prep_shot_sums(const float* __restrict__ xs) {
    int gw = blockIdx.x * 8 + (threadIdx.x >> 5);
    int lane = threadIdx.x & 31;
    int bw = gw / C_;
    int c = gw - bw * C_;
    const float* base = xs + (size_t)bw * (S_ * C_ * HW_);
    float ss = 0.f, sm = 0.f;
    for (int j = lane; j < S_ * HW_; j += 32) {
        int s = j / HW_;
        int p = j - s * HW_;
        float v = base[((size_t)s * C_ + c) * HW_ + p];
        ss += v * v;
        sm += v;
    }
    ss = warpSum(ss);
    sm = warpSum(sm);
    if (lane == 0) {
        g_sup_inv[bw * C_ + c] = rsqrtf(ss);
        g_proto[bw * C_ + c] = sm * (1.0f / (S_ * HW_));
    }
}

// Kernel 2: normalize prototypes. grid=40, block=256.
__global__ void prep_proto_norm() {
    int bw = blockIdx.x;
    int tid = threadIdx.x;
    float local = 0.f;
    for (int c = tid; c < C_; c += 256) {
        float v = g_proto[bw * C_ + c];
        local += v * v;
    }
    local = warpSum(local);
    __shared__ float part[8];
    if ((tid & 31) == 0) part[tid >> 5] = local;
    __syncthreads();
    __shared__ float sinv;
    if (tid == 0) {
        float t = 0.f;
        #pragma unroll
        for (int k = 0; k < 8; k++) t += part[k];
        sinv = rsqrtf(t);
    }
    __syncthreads();
    for (int c = tid; c < C_; c += 256)
        g_pn[bw * C_ + c] = g_proto[bw * C_ + c] * sinv;
}

// ---------------------------------------------------------------------------
// Kernel 3: pack A (query descriptors, scaled, fp16, fragment order)
// + fused query stats (qn). grid = B*Q = 600, block = 256.
// ---------------------------------------------------------------------------
#define CCH 64
__global__ void __launch_bounds__(256) packA(const float* __restrict__ xq) {
    int bq = blockIdx.x;
    int b = bq / Q_;
    int q = bq - b * Q_;
    int tid = threadIdx.x;
    const float* src = xq + (size_t)bq * (C_ * HW_);

    __shared__ float s_t[CCH][101];
    __shared__ float csum[C_];
    __shared__ float persq[HW_];
    __shared__ float qinv[HW_];
    __shared__ float part[8];
    __shared__ float sinv;

    for (int i = tid; i < C_; i += 256) csum[i] = 0.f;
    if (tid < HW_) persq[tid] = 0.f;
    __syncthreads();

    // pass 1: stats
    for (int cc0 = 0; cc0 < C_; cc0 += CCH) {
        for (int idx = tid; idx < CCH * HW_; idx += 256) {
            int cc = idx / HW_;
            int p = idx - cc * HW_;
            s_t[cc][p] = src[(size_t)(cc0 + cc) * HW_ + p];
        }
        __syncthreads();
        int wid = tid >> 5, lane = tid & 31;
        for (int cc = wid; cc < CCH; cc += 8) {
            float sm = 0.f;
            #pragma unroll
            for (int pp = lane; pp < HW_; pp += 32) sm += s_t[cc][pp];
            sm = warpSum(sm);
            if (lane == 0) csum[cc0 + cc] += sm;
        }
        if (tid < HW_) {
            float acc = 0.f;
            #pragma unroll 8
            for (int cc = 0; cc < CCH; cc++) {
                float v = s_t[cc][tid];
                acc += v * v;
            }
            persq[tid] += acc;
        }
        __syncthreads();
    }

    if (tid < HW_) qinv[tid] = rsqrtf(persq[tid]);
    float local = 0.f;
    for (int c = tid; c < C_; c += 256) {
        float m = csum[c] * (1.0f / HW_);
        local += m * m;
    }
    local = warpSum(local);
    if ((tid & 31) == 0) part[tid >> 5] = local;
    __syncthreads();
    if (tid == 0) {
        float t = 0.f;
        #pragma unroll
        for (int k = 0; k < 8; k++) t += part[k];
        sinv = rsqrtf(t);
    }
    __syncthreads();
    for (int c = tid; c < C_; c += 256)
        g_qn[bq * C_ + c] = csum[c] * (1.0f / HW_) * sinv;

    // pass 2: write scaled fp16 pairs to g_A in fragment order
    for (int cc0 = 0; cc0 < C_; cc0 += CCH) {
        __syncthreads();
        for (int idx = tid; idx < CCH * HW_; idx += 256) {
            int cc = idx / HW_;
            int p = idx - cc * HW_;
            s_t[cc][p] = src[(size_t)(cc0 + cc) * HW_ + p];
        }
        __syncthreads();
        for (int idx = tid; idx < (CCH / 2) * HW_; idx += 256) {
            int cc2 = idx & 31;
            int p = idx >> 5;
            int c = cc0 + cc2 * 2;        // even channel of the pair
            int k16 = c >> 4;
            int c16 = c & 15;             // even
            int r = q * HW_ + p;
            int mt = r >> 7;
            int rl = r & 127;
            int mg = rl >> 4;
            int rr = rl & 15;
            int tig = (c16 & 7) >> 1;
            int reg = (rr >> 3) | ((c16 >> 3) << 1);
            int lane = ((rr & 7) << 2) | tig;
            float v0 = s_t[cc2 * 2][p] * qinv[p];
            float v1 = s_t[cc2 * 2 + 1][p] * qinv[p];
            size_t tile = ((size_t)(b * MT_ + mt) * K16_ + k16) * 8 + mg;
            g_A[tile * 128 + lane * 4 + reg] = pack_h2(v0, v1);
        }
    }
}

// ---------------------------------------------------------------------------
// Kernel 4: pack B (support descriptors, scaled, fp16, fragment order).
// grid = B*W*S = 200, block = 256.
// ---------------------------------------------------------------------------
__global__ void __launch_bounds__(256) packB(const float* __restrict__ xs) {
    int bws = blockIdx.x;
    int s = bws % S_;
    int bw = bws / S_;
    int tid = threadIdx.x;
    const float* src = xs + (size_t)(bw * S_ + s) * (C_ * HW_);

    __shared__ float s_t[CCH][101];

    for (int cc0 = 0; cc0 < C_; cc0 += CCH) {
        __syncthreads();
        for (int idx = tid; idx < CCH * HW_; idx += 256) {
            int cc = idx / HW_;
            int p = idx - cc * HW_;
            s_t[cc][p] = src[(size_t)(cc0 + cc) * HW_ + p];
        }
        __syncthreads();
        for (int idx = tid; idx < (CCH / 2) * HW_; idx += 256) {
            int cc2 = idx & 31;
            int p = idx >> 5;
            int c = cc0 + cc2 * 2;
            int k16 = c >> 4;
            int c16 = c & 15;
            int d = s * HW_ + p;          // 0..499
            int n16 = d >> 4;
            int nsub = (d >> 3) & 1;
            int nl = d & 7;
            int tig = (c16 & 7) >> 1;
            int reg = c16 >> 3;
            int lane = (nl << 2) | tig;
            float v0 = s_t[cc2 * 2][p] * g_sup_inv[bw * C_ + c];
            float v1 = s_t[cc2 * 2 + 1][p] * g_sup_inv[bw * C_ + c + 1];
            size_t tile = ((size_t)bw * K16_ + k16) * 32 + n16;
            g_Bm[tile * 128 + lane * 4 + nsub * 2 + reg] = pack_h2(v0, v1);
        }
    }
}

// ---------------------------------------------------------------------------
// Kernel 5: mma.sync fp16 GEMM (fp16 acc, fp32 promote every 8 K-steps)
// with cp.async double-buffered smem staging. grid=(59,40), block=256.
// 8 warps: 4(M) x 2(N). CTA tile M=128, N=512 in 4 chunks of 128, K=640.
// Per (nc,k) stage: 8 A tiles (4KB) + 8 B tiles (4KB) = 8KB.
// ---------------------------------------------------------------------------
__global__ void __launch_bounds__(256) gemm_topk() {
    __shared__ uint4 stg[2][512];   // [stage][ A: 0..255 | B: 256..511 ]

    int mt = blockIdx.x;
    int bw = blockIdx.y;
    int b = bw / W_;
    int tid = threadIdx.x;
    int lane = tid & 31;
    int wid = tid >> 5;
    int wm = wid & 3;
    int wn = wid >> 2;

    const uint4* Ab = (const uint4*)g_A + (size_t)(b * MT_ + mt) * (K16_ * 8 * 32);
    const uint4* Bb = (const uint4*)g_Bm + (size_t)bw * (K16_ * 32 * 32);

    uint32_t stgAddr = smem_u32p(stg);
    int cpTile = tid >> 5;            // 0..7
    int cpLane = tid & 31;

    float t5[4][5];
    #pragma unroll
    for (int i = 0; i < 4; i++)
        #pragma unroll
        for (int s = 0; s < 5; s++) t5[i][s] = -1e30f;

    #pragma unroll 1
    for (int nc = 0; nc < 4; nc++) {
        float d[2][8][4];
        #pragma unroll
        for (int i = 0; i < 2; i++)
            #pragma unroll
            for (int j = 0; j < 8; j++)
                #pragma unroll
                for (int e = 0; e < 4; e++) d[i][j][e] = 0.f;

        uint32_t dh[2][8][2];
        int nb0 = nc * 8;

        // prologue: stage k=0 into buffer 0
        {
            cpasync16(stgAddr + (size_t)(cpTile * 32 + cpLane) * 16,
                      Ab + ((0 * 8 + cpTile) << 5) + cpLane);
            cpasync16(stgAddr + (size_t)(256 + cpTile * 32 + cpLane) * 16,
                      Bb + (((0 << 5) + nb0 + cpTile) << 5) + cpLane);
            asm volatile("cp.async.commit_group;" ::: "memory");
        }

        #pragma unroll 1
        for (int k = 0; k < K16_; k++) {
            asm volatile("cp.async.wait_group 0;" ::: "memory");
            __syncthreads();   // buf[k&1] visible; all warps done reading buf[(k+1)&1]
            int st = k & 1;
            if (k + 1 < K16_) {
                int st2 = st ^ 1;
                cpasync16(stgAddr + (size_t)((st2 * 512) + cpTile * 32 + cpLane) * 16,
                          Ab + (((k + 1) * 8 + cpTile) << 5) + cpLane);
                cpasync16(stgAddr + (size_t)((st2 * 512) + 256 + cpTile * 32 + cpLane) * 16,
                          Bb + ((((k + 1) << 5) + nb0 + cpTile) << 5) + cpLane);
                asm volatile("cp.async.commit_group;" ::: "memory");
            }

            if ((k & 7) == 0) {
                #pragma unroll
                for (int i = 0; i < 2; i++)
                    #pragma unroll
                    for (int j = 0; j < 8; j++) { dh[i][j][0] = 0u; dh[i][j][1] = 0u; }
            }

            uint4 a0 = stg[st][(wm * 2 + 0) * 32 + lane];
            uint4 a1 = stg[st][(wm * 2 + 1) * 32 + lane];
            uint4 b0 = stg[st][256 + (wn * 4 + 0) * 32 + lane];
            uint4 b1 = stg[st][256 + (wn * 4 + 1) * 32 + lane];
            uint4 b2 = stg[st][256 + (wn * 4 + 2) * 32 + lane];
            uint4 b3 = stg[st][256 + (wn * 4 + 3) * 32 + lane];

            mma16h(dh[0][0], a0, b0.x, b0.y);  mma16h(dh[0][1], a0, b0.z, b0.w);
            mma16h(dh[0][2], a0, b1.x, b1.y);  mma16h(dh[0][3], a0, b1.z, b1.w);
            mma16h(dh[0][4], a0, b2.x, b2.y);  mma16h(dh[0][5], a0, b2.z, b2.w);
            mma16h(dh[0][6], a0, b3.x, b3.y);  mma16h(dh[0][7], a0, b3.z, b3.w);
            mma16h(dh[1][0], a1, b0.x, b0.y);  mma16h(dh[1][1], a1, b0.z, b0.w);
            mma16h(dh[1][2], a1, b1.x, b1.y);  mma16h(dh[1][3], a1, b1.z, b1.w);
            mma16h(dh[1][4], a1, b2.x, b2.y);  mma16h(dh[1][5], a1, b2.z, b2.w);
            mma16h(dh[1][6], a1, b3.x, b3.y);  mma16h(dh[1][7], a1, b3.z, b3.w);

            if ((k & 7) == 7) {
                #pragma unroll
                for (int i = 0; i < 2; i++)
                    #pragma unroll
                    for (int j = 0; j < 8; j++) {
                        float2 f0 = __half22float2(*(__half2*)&dh[i][j][0]);
                        float2 f1 = __half22float2(*(__half2*)&dh[i][j][1]);
                        d[i][j][0] += f0.x;
                        d[i][j][1] += f0.y;
                        d[i][j][2] += f1.x;
                        d[i][j][3] += f1.y;
                    }
            }
        }
        __syncthreads();   // all reads of both buffers done before next nc restages

        // fold this n-chunk into per-thread top-5 (rows: i*2+h)
        int cbase = nc * 128 + wn * 64 + (lane & 3) * 2;
        #pragma unroll
        for (int i = 0; i < 2; i++)
            #pragma unroll
            for (int h = 0; h < 2; h++)
                #pragma unroll
                for (int j = 0; j < 8; j++)
                    #pragma unroll
                    for (int e = 0; e < 2; e++) {
                        int c = cbase + j * 8 + e;
                        float v = d[i][j][h * 2 + e];
                        if (c < 500) ins5(t5[i * 2 + h], v);
                    }
    }

    // merge per-row top-5 candidates via smem
    __shared__ float s5[128][42];
    int owner = wn * 4 + (lane & 3);   // 0..7
    #pragma unroll
    for (int i = 0; i < 2; i++)
        #pragma unroll
        for (int h = 0; h < 2; h++) {
            int rl = wm * 32 + i * 16 + h * 8 + (lane >> 2);
            #pragma unroll
            for (int s = 0; s < 5; s++)
                s5[rl][owner * 5 + s] = t5[i * 2 + h][s];
        }
    __syncthreads();

    if (tid < 128) {
        float t[5] = {-1e30f, -1e30f, -1e30f, -1e30f, -1e30f};
        #pragma unroll
        for (int s = 0; s < 40; s++) ins5(t, s5[tid][s]);
        int r = mt * 128 + tid;
        if (r < MROWS_)
            g_rowsum[(size_t)bw * MROWS_ + r] = t[0] + t[1] + t[2] + t[3] + t[4];
    }
}

// ---------------------------------------------------------------------------
// Kernel 6: finalize. grid = B*Q*W = 3000, block = 128.
// ---------------------------------------------------------------------------
__global__ void finalize(const float* __restrict__ r_cos, const float* __restrict__ r_dn4,
                         float* __restrict__ out) {
    int idx = blockIdx.x;
    int w = idx % W_;
    int q = (idx / W_) % Q_;
    int b = idx / (W_ * Q_);
    int tid = threadIdx.x;
    int bw = b * W_ + w;
    int bq = b * Q_ + q;

    float cosd = 0.f;
    for (int c = tid; c < C_; c += 128)
        cosd += g_qn[bq * C_ + c] * g_pn[bw * C_ + c];
    float dn4 = 0.f;
    if (tid < HW_)
        dn4 = g_rowsum[(size_t)bw * MROWS_ + q * HW_ + tid];

    cosd = warpSum(cosd);
    dn4 = warpSum(dn4);
    __shared__ float pc[4], pd[4];
    if ((tid & 31) == 0) { pc[tid >> 5] = cosd; pd[tid >> 5] = dn4; }
    __syncthreads();
    if (tid == 0) {
        float c2 = pc[0] + pc[1] + pc[2] + pc[3];
        float a = pd[0] + pd[1] + pd[2] + pd[3];
        out[idx] = r_cos[0] * c2 + r_dn4[0] * (a * (1.0f / NK_));
    }
}

// ---------------------------------------------------------------------------
extern "C" void kernel_launch(void* const* d_in, const int* in_sizes, int n_in,
                              void* d_out, int out_size) {
    const float* x_shot  = (const float*)d_in[0];
    const float* x_query = (const float*)d_in[1];
    const float* r_cos   = (const float*)d_in[2];
    const float* r_dn4   = (const float*)d_in[3];
    float* out = (float*)d_out;

    prep_shot_sums<<<3200, 256>>>(x_shot);
    prep_proto_norm<<<40, 256>>>();
    packA<<<B_ * Q_, 256>>>(x_query);
    packB<<<B_ * W_ * S_, 256>>>(x_shot);
    gemm_topk<<<dim3(MT_, B_ * W_), 256>>>();
    finalize<<<B_ * Q_ * W_, 128>>>(r_cos, r_dn4, out);
}

// round 8
// speedup vs baseline: 1.0965x; 1.0965x over previous
#include <cuda_runtime.h>
#include <cuda_fp16.h>
#include <cstdint>

// Problem constants
#define B_ 8
#define W_ 5
#define S_ 5
#define C_ 640
#define HW_ 100
#define Q_ 75
#define NK_ 5

#define MT_ 59            // M-tiles of 128 over 7500 rows (padded to 7552)
#define MROWS_ 7500
#define K16_ 40           // K steps of 16 (C=640)

// ---------------------------------------------------------------------------
// Scratch (zero-init; pad regions never written -> zeros).
// A: [b][mt][k16][mg(8)] 16x16 fp16 tiles in m16n8k16 A-fragment order
//    (scaled by qd_inv).
// B: [bw][k16][n16(32)] paired 16x8 fp16 tiles (scaled by sup_inv).
// ---------------------------------------------------------------------------
__device__ uint32_t g_A[B_ * MT_ * K16_ * 8 * 128];    // 77.3 MB
__device__ uint32_t g_Bm[B_ * W_ * K16_ * 32 * 128];   // 26.2 MB
__device__ float g_rowsum[B_ * W_ * MROWS_];
__device__ float g_sup_inv[B_ * W_ * C_];
__device__ float g_proto[B_ * W_ * C_];
__device__ float g_pn[B_ * W_ * C_];
__device__ float g_qn[B_ * Q_ * C_];

__device__ __forceinline__ float warpSum(float v) {
    #pragma unroll
    for (int o = 16; o; o >>= 1) v += __shfl_xor_sync(0xffffffffu, v, o);
    return v;
}

// fp16-accumulate HMMA
__device__ __forceinline__ void mma16h(uint32_t* d, uint4 a, uint32_t b0, uint32_t b1) {
    asm volatile(
        "mma.sync.aligned.m16n8k16.row.col.f16.f16.f16.f16 "
        "{%0,%1}, {%2,%3,%4,%5}, {%6,%7}, {%0,%1};"
        : "+r"(d[0]), "+r"(d[1])
        : "r"(a.x), "r"(a.y), "r"(a.z), "r"(a.w), "r"(b0), "r"(b1));
}

__device__ __forceinline__ void mma_block(uint32_t dh[2][8][2],
                                          uint4 a0, uint4 a1,
                                          uint4 b0, uint4 b1, uint4 b2, uint4 b3) {
    mma16h(dh[0][0], a0, b0.x, b0.y);  mma16h(dh[0][1], a0, b0.z, b0.w);
    mma16h(dh[0][2], a0, b1.x, b1.y);  mma16h(dh[0][3], a0, b1.z, b1.w);
    mma16h(dh[0][4], a0, b2.x, b2.y);  mma16h(dh[0][5], a0, b2.z, b2.w);
    mma16h(dh[0][6], a0, b3.x, b3.y);  mma16h(dh[0][7], a0, b3.z, b3.w);
    mma16h(dh[1][0], a1, b0.x, b0.y);  mma16h(dh[1][1], a1, b0.z, b0.w);
    mma16h(dh[1][2], a1, b1.x, b1.y);  mma16h(dh[1][3], a1, b1.z, b1.w);
    mma16h(dh[1][4], a1, b2.x, b2.y);  mma16h(dh[1][5], a1, b2.z, b2.w);
    mma16h(dh[1][6], a1, b3.x, b3.y);  mma16h(dh[1][7], a1, b3.z, b3.w);
}

__device__ __forceinline__ void ins5(float (&t)[5], float v) {
    if (v > t[0]) {
        t[0] = v;
        if (t[0] > t[1]) { float x = t[1]; t[1] = t[0]; t[0] = x;
            if (t[1] > t[2]) { x = t[2]; t[2] = t[1]; t[1] = x;
                if (t[2] > t[3]) { x = t[3]; t[3] = t[2]; t[2] = x;
                    if (t[3] > t[4]) { x = t[4]; t[4] = t[3]; t[3] = x; } } } }
    }
}

__device__ __forceinline__ uint32_t pack_h2(float v0, float v1) {
    __half2 h = __floats2half2_rn(v0, v1);   // .x (low) = v0
    return *(uint32_t*)&h;
}

// ---------------------------------------------------------------------------
// Kernel 1: per-(bw,c) support sums. One warp per (bw,c). grid=3200, block=256.
// ---------------------------------------------------------------------------
__global__ void prep_shot_sums(const float* __restrict__ xs) {
    int gw = blockIdx.x * 8 + (threadIdx.x >> 5);
    int lane = threadIdx.x & 31;
    int bw = gw / C_;
    int c = gw - bw * C_;
    const float* base = xs + (size_t)bw * (S_ * C_ * HW_);
    float ss = 0.f, sm = 0.f;
    for (int j = lane; j < S_ * HW_; j += 32) {
        int s = j / HW_;
        int p = j - s * HW_;
        float v = base[((size_t)s * C_ + c) * HW_ + p];
        ss += v * v;
        sm += v;
    }
    ss = warpSum(ss);
    sm = warpSum(sm);
    if (lane == 0) {
        g_sup_inv[bw * C_ + c] = rsqrtf(ss);
        g_proto[bw * C_ + c] = sm * (1.0f / (S_ * HW_));
    }
}

// Kernel 2: normalize prototypes. grid=40, block=256.
__global__ void prep_proto_norm() {
    int bw = blockIdx.x;
    int tid = threadIdx.x;
    float local = 0.f;
    for (int c = tid; c < C_; c += 256) {
        float v = g_proto[bw * C_ + c];
        local += v * v;
    }
    local = warpSum(local);
    __shared__ float part[8];
    if ((tid & 31) == 0) part[tid >> 5] = local;
    __syncthreads();
    __shared__ float sinv;
    if (tid == 0) {
        float t = 0.f;
        #pragma unroll
        for (int k = 0; k < 8; k++) t += part[k];
        sinv = rsqrtf(t);
    }
    __syncthreads();
    for (int c = tid; c < C_; c += 256)
        g_pn[bw * C_ + c] = g_proto[bw * C_ + c] * sinv;
}

// ---------------------------------------------------------------------------
// Kernel 3: pack A (query descriptors, scaled, fp16, fragment order)
// + fused query stats (qn). grid = B*Q = 600, block = 256.
// ---------------------------------------------------------------------------
#define CCH 64
__global__ void __launch_bounds__(256) packA(const float* __restrict__ xq) {
    int bq = blockIdx.x;
    int b = bq / Q_;
    int q = bq - b * Q_;
    int tid = threadIdx.x;
    const float* src = xq + (size_t)bq * (C_ * HW_);

    __shared__ float s_t[CCH][101];
    __shared__ float csum[C_];
    __shared__ float persq[HW_];
    __shared__ float qinv[HW_];
    __shared__ float part[8];
    __shared__ float sinv;

    for (int i = tid; i < C_; i += 256) csum[i] = 0.f;
    if (tid < HW_) persq[tid] = 0.f;
    __syncthreads();

    // pass 1: stats
    for (int cc0 = 0; cc0 < C_; cc0 += CCH) {
        for (int idx = tid; idx < CCH * HW_; idx += 256) {
            int cc = idx / HW_;
            int p = idx - cc * HW_;
            s_t[cc][p] = src[(size_t)(cc0 + cc) * HW_ + p];
        }
        __syncthreads();
        int wid = tid >> 5, lane = tid & 31;
        for (int cc = wid; cc < CCH; cc += 8) {
            float sm = 0.f;
            #pragma unroll
            for (int pp = lane; pp < HW_; pp += 32) sm += s_t[cc][pp];
            sm = warpSum(sm);
            if (lane == 0) csum[cc0 + cc] += sm;
        }
        if (tid < HW_) {
            float acc = 0.f;
            #pragma unroll 8
            for (int cc = 0; cc < CCH; cc++) {
                float v = s_t[cc][tid];
                acc += v * v;
            }
            persq[tid] += acc;
        }
        __syncthreads();
    }

    if (tid < HW_) qinv[tid] = rsqrtf(persq[tid]);
    float local = 0.f;
    for (int c = tid; c < C_; c += 256) {
        float m = csum[c] * (1.0f / HW_);
        local += m * m;
    }
    local = warpSum(local);
    if ((tid & 31) == 0) part[tid >> 5] = local;
    __syncthreads();
    if (tid == 0) {
        float t = 0.f;
        #pragma unroll
        for (int k = 0; k < 8; k++) t += part[k];
        sinv = rsqrtf(t);
    }
    __syncthreads();
    for (int c = tid; c < C_; c += 256)
        g_qn[bq * C_ + c] = csum[c] * (1.0f / HW_) * sinv;

    // pass 2: write scaled fp16 pairs to g_A in fragment order
    for (int cc0 = 0; cc0 < C_; cc0 += CCH) {
        __syncthreads();
        for (int idx = tid; idx < CCH * HW_; idx += 256) {
            int cc = idx / HW_;
            int p = idx - cc * HW_;
            s_t[cc][p] = src[(size_t)(cc0 + cc) * HW_ + p];
        }
        __syncthreads();
        for (int idx = tid; idx < (CCH / 2) * HW_; idx += 256) {
            int cc2 = idx & 31;
            int p = idx >> 5;
            int c = cc0 + cc2 * 2;        // even channel of the pair
            int k16 = c >> 4;
            int c16 = c & 15;             // even
            int r = q * HW_ + p;
            int mt = r >> 7;
            int rl = r & 127;
            int mg = rl >> 4;
            int rr = rl & 15;
            int tig = (c16 & 7) >> 1;
            int reg = (rr >> 3) | ((c16 >> 3) << 1);
            int lane = ((rr & 7) << 2) | tig;
            float v0 = s_t[cc2 * 2][p] * qinv[p];
            float v1 = s_t[cc2 * 2 + 1][p] * qinv[p];
            size_t tile = ((size_t)(b * MT_ + mt) * K16_ + k16) * 8 + mg;
            g_A[tile * 128 + lane * 4 + reg] = pack_h2(v0, v1);
        }
    }
}

// ---------------------------------------------------------------------------
// Kernel 4: pack B (support descriptors, scaled, fp16, fragment order).
// grid = B*W*S = 200, block = 256.
// ---------------------------------------------------------------------------
__global__ void __launch_bounds__(256) packB(const float* __restrict__ xs) {
    int bws = blockIdx.x;
    int s = bws % S_;
    int bw = bws / S_;
    int tid = threadIdx.x;
    const float* src = xs + (size_t)(bw * S_ + s) * (C_ * HW_);

    __shared__ float s_t[CCH][101];

    for (int cc0 = 0; cc0 < C_; cc0 += CCH) {
        __syncthreads();
        for (int idx = tid; idx < CCH * HW_; idx += 256) {
            int cc = idx / HW_;
            int p = idx - cc * HW_;
            s_t[cc][p] = src[(size_t)(cc0 + cc) * HW_ + p];
        }
        __syncthreads();
        for (int idx = tid; idx < (CCH / 2) * HW_; idx += 256) {
            int cc2 = idx & 31;
            int p = idx >> 5;
            int c = cc0 + cc2 * 2;
            int k16 = c >> 4;
            int c16 = c & 15;
            int d = s * HW_ + p;          // 0..499
            int n16 = d >> 4;
            int nsub = (d >> 3) & 1;
            int nl = d & 7;
            int tig = (c16 & 7) >> 1;
            int reg = c16 >> 3;
            int lane = (nl << 2) | tig;
            float v0 = s_t[cc2 * 2][p] * g_sup_inv[bw * C_ + c];
            float v1 = s_t[cc2 * 2 + 1][p] * g_sup_inv[bw * C_ + c + 1];
            size_t tile = ((size_t)bw * K16_ + k16) * 32 + n16;
            g_Bm[tile * 128 + lane * 4 + nsub * 2 + reg] = pack_h2(v0, v1);
        }
    }
}

// ---------------------------------------------------------------------------
// Kernel 5: mma.sync fp16 GEMM (fp16 acc, fp32 promote every 8 K-steps)
// with register double-buffered prefetch. grid=(59,40), block=256.
// 8 warps: 4(M) x 2(N). CTA tile M=128, N=512 in 4 chunks of 128, K=640.
// ---------------------------------------------------------------------------
__global__ void __launch_bounds__(256) gemm_topk() {
    int mt = blockIdx.x;
    int bw = blockIdx.y;
    int b = bw / W_;
    int tid = threadIdx.x;
    int lane = tid & 31;
    int wid = tid >> 5;
    int wm = wid & 3;
    int wn = wid >> 2;

    const uint4* Ab = (const uint4*)g_A + (size_t)(b * MT_ + mt) * (K16_ * 8 * 32);
    const uint4* Bb = (const uint4*)g_Bm + (size_t)bw * (K16_ * 32 * 32);

    float t5[4][5];
    #pragma unroll
    for (int i = 0; i < 4; i++)
        #pragma unroll
        for (int s = 0; s < 5; s++) t5[i][s] = -1e30f;

    #pragma unroll 1
    for (int nc = 0; nc < 4; nc++) {
        float d[2][8][4];
        #pragma unroll
        for (int i = 0; i < 2; i++)
            #pragma unroll
            for (int j = 0; j < 8; j++)
                #pragma unroll
                for (int e = 0; e < 4; e++) d[i][j][e] = 0.f;

        uint32_t dh[2][8][2];
        int nb0 = nc * 8 + wn * 4;        // pair-tile index base

        // prologue: load k=0 fragments
        uint4 a0 = Ab[((0 * 8 + wm * 2 + 0) << 5) + lane];
        uint4 a1 = Ab[((0 * 8 + wm * 2 + 1) << 5) + lane];
        uint4 b0 = Bb[(((0 << 5) + nb0 + 0) << 5) + lane];
        uint4 b1 = Bb[(((0 << 5) + nb0 + 1) << 5) + lane];
        uint4 b2 = Bb[(((0 << 5) + nb0 + 2) << 5) + lane];
        uint4 b3 = Bb[(((0 << 5) + nb0 + 3) << 5) + lane];

        #pragma unroll 1
        for (int k = 0; k < K16_ - 1; k++) {
            // prefetch k+1 into shadow registers (lands during the MMA block)
            int kn = k + 1;
            uint4 na0 = Ab[((kn * 8 + wm * 2 + 0) << 5) + lane];
            uint4 na1 = Ab[((kn * 8 + wm * 2 + 1) << 5) + lane];
            uint4 nb0v = Bb[(((kn << 5) + nb0 + 0) << 5) + lane];
            uint4 nb1v = Bb[(((kn << 5) + nb0 + 1) << 5) + lane];
            uint4 nb2v = Bb[(((kn << 5) + nb0 + 2) << 5) + lane];
            uint4 nb3v = Bb[(((kn << 5) + nb0 + 3) << 5) + lane];

            if ((k & 7) == 0) {
                #pragma unroll
                for (int i = 0; i < 2; i++)
                    #pragma unroll
                    for (int j = 0; j < 8; j++) { dh[i][j][0] = 0u; dh[i][j][1] = 0u; }
            }

            mma_block(dh, a0, a1, b0, b1, b2, b3);

            if ((k & 7) == 7) {
                #pragma unroll
                for (int i = 0; i < 2; i++)
                    #pragma unroll
                    for (int j = 0; j < 8; j++) {
                        float2 f0 = __half22float2(*(__half2*)&dh[i][j][0]);
                        float2 f1 = __half22float2(*(__half2*)&dh[i][j][1]);
                        d[i][j][0] += f0.x;
                        d[i][j][1] += f0.y;
                        d[i][j][2] += f1.x;
                        d[i][j][3] += f1.y;
                    }
            }

            a0 = na0; a1 = na1;
            b0 = nb0v; b1 = nb1v; b2 = nb2v; b3 = nb3v;
        }

        // final k-step (k = K16_-1; (k & 7)==7 since K16_=40)
        mma_block(dh, a0, a1, b0, b1, b2, b3);
        #pragma unroll
        for (int i = 0; i < 2; i++)
            #pragma unroll
            for (int j = 0; j < 8; j++) {
                float2 f0 = __half22float2(*(__half2*)&dh[i][j][0]);
                float2 f1 = __half22float2(*(__half2*)&dh[i][j][1]);
                d[i][j][0] += f0.x;
                d[i][j][1] += f0.y;
                d[i][j][2] += f1.x;
                d[i][j][3] += f1.y;
            }

        // fold this n-chunk into per-thread top-5 (rows: i*2+h)
        int cbase = nc * 128 + wn * 64 + (lane & 3) * 2;
        #pragma unroll
        for (int i = 0; i < 2; i++)
            #pragma unroll
            for (int h = 0; h < 2; h++)
                #pragma unroll
                for (int j = 0; j < 8; j++)
                    #pragma unroll
                    for (int e = 0; e < 2; e++) {
                        int c = cbase + j * 8 + e;
                        float v = d[i][j][h * 2 + e];
                        if (c < 500) ins5(t5[i * 2 + h], v);
                    }
    }

    // merge per-row top-5 candidates via smem
    __shared__ float s5[128][42];
    int owner = wn * 4 + (lane & 3);   // 0..7
    #pragma unroll
    for (int i = 0; i < 2; i++)
        #pragma unroll
        for (int h = 0; h < 2; h++) {
            int rl = wm * 32 + i * 16 + h * 8 + (lane >> 2);
            #pragma unroll
            for (int s = 0; s < 5; s++)
                s5[rl][owner * 5 + s] = t5[i * 2 + h][s];
        }
    __syncthreads();

    if (tid < 128) {
        float t[5] = {-1e30f, -1e30f, -1e30f, -1e30f, -1e30f};
        #pragma unroll
        for (int s = 0; s < 40; s++) ins5(t, s5[tid][s]);
        int r = mt * 128 + tid;
        if (r < MROWS_)
            g_rowsum[(size_t)bw * MROWS_ + r] = t[0] + t[1] + t[2] + t[3] + t[4];
    }
}

// ---------------------------------------------------------------------------
// Kernel 6: finalize. grid = B*Q*W = 3000, block = 128.
// ---------------------------------------------------------------------------
__global__ void finalize(const float* __restrict__ r_cos, const float* __restrict__ r_dn4,
                         float* __restrict__ out) {
    int idx = blockIdx.x;
    int w = idx % W_;
    int q = (idx / W_) % Q_;
    int b = idx / (W_ * Q_);
    int tid = threadIdx.x;
    int bw = b * W_ + w;
    int bq = b * Q_ + q;

    float cosd = 0.f;
    for (int c = tid; c < C_; c += 128)
        cosd += g_qn[bq * C_ + c] * g_pn[bw * C_ + c];
    float dn4 = 0.f;
    if (tid < HW_)
        dn4 = g_rowsum[(size_t)bw * MROWS_ + q * HW_ + tid];

    cosd = warpSum(cosd);
    dn4 = warpSum(dn4);
    __shared__ float pc[4], pd[4];
    if ((tid & 31) == 0) { pc[tid >> 5] = cosd; pd[tid >> 5] = dn4; }
    __syncthreads();
    if (tid == 0) {
        float c2 = pc[0] + pc[1] + pc[2] + pc[3];
        float a = pd[0] + pd[1] + pd[2] + pd[3];
        out[idx] = r_cos[0] * c2 + r_dn4[0] * (a * (1.0f / NK_));
    }
}

// ---------------------------------------------------------------------------
extern "C" void kernel_launch(void* const* d_in, const int* in_sizes, int n_in,
                              void* d_out, int out_size) {
    const float* x_shot  = (const float*)d_in[0];
    const float* x_query = (const float*)d_in[1];
    const float* r_cos   = (const float*)d_in[2];
    const float* r_dn4   = (const float*)d_in[3];
    float* out = (float*)d_out;

    prep_shot_sums<<<3200, 256>>>(x_shot);
    prep_proto_norm<<<40, 256>>>();
    packA<<<B_ * Q_, 256>>>(x_query);
    packB<<<B_ * W_ * S_, 256>>>(x_shot);
    gemm_topk<<<dim3(MT_, B_ * W_), 256>>>();
    finalize<<<B_ * Q_ * W_, 128>>>(r_cos, r_dn4, out);
}

// round 9
// speedup vs baseline: 1.1064x; 1.0090x over previous
#include <cuda_runtime.h>
#include <cuda_fp16.h>
#include <cstdint>

// Problem constants
#define B_ 8
#define W_ 5
#define S_ 5
#define C_ 640
#define HW_ 100
#define Q_ 75
#define NK_ 5

#define MT_ 59            // M-tiles of 128 over 7500 rows (padded to 7552)
#define MROWS_ 7500
#define K16_ 40           // K steps of 16 (C=640)

// ---------------------------------------------------------------------------
// Scratch (zero-init; pad regions never written -> zeros).
// A: [b][mt][k16][mg(8)] 16x16 fp16 tiles in m16n8k16 A-fragment order
//    (UNSCALED; qd_inv applied in GEMM epilogue — rank-invariant).
// B: [bw][k16][n16(32)] paired 16x8 fp16 tiles (scaled by sup_inv).
// ---------------------------------------------------------------------------
__device__ uint32_t g_A[B_ * MT_ * K16_ * 8 * 128];    // 77.3 MB
__device__ uint32_t g_Bm[B_ * W_ * K16_ * 32 * 128];   // 26.2 MB
__device__ float g_rowsum[B_ * W_ * MROWS_];
__device__ float g_sup_inv[B_ * W_ * C_];
__device__ float g_proto[B_ * W_ * C_];
__device__ float g_pn[B_ * W_ * C_];
__device__ float g_qn[B_ * Q_ * C_];
__device__ float g_qd_inv[B_ * MROWS_];                // [b][q*100+p]

__device__ __forceinline__ float warpSum(float v) {
    #pragma unroll
    for (int o = 16; o; o >>= 1) v += __shfl_xor_sync(0xffffffffu, v, o);
    return v;
}

// fp16-accumulate HMMA
__device__ __forceinline__ void mma16h(uint32_t* d, uint4 a, uint32_t b0, uint32_t b1) {
    asm volatile(
        "mma.sync.aligned.m16n8k16.row.col.f16.f16.f16.f16 "
        "{%0,%1}, {%2,%3,%4,%5}, {%6,%7}, {%0,%1};"
        : "+r"(d[0]), "+r"(d[1])
        : "r"(a.x), "r"(a.y), "r"(a.z), "r"(a.w), "r"(b0), "r"(b1));
}

__device__ __forceinline__ void mma_block(uint32_t dh[2][8][2],
                                          uint4 a0, uint4 a1,
                                          uint4 b0, uint4 b1, uint4 b2, uint4 b3) {
    mma16h(dh[0][0], a0, b0.x, b0.y);  mma16h(dh[0][1], a0, b0.z, b0.w);
    mma16h(dh[0][2], a0, b1.x, b1.y);  mma16h(dh[0][3], a0, b1.z, b1.w);
    mma16h(dh[0][4], a0, b2.x, b2.y);  mma16h(dh[0][5], a0, b2.z, b2.w);
    mma16h(dh[0][6], a0, b3.x, b3.y);  mma16h(dh[0][7], a0, b3.z, b3.w);
    mma16h(dh[1][0], a1, b0.x, b0.y);  mma16h(dh[1][1], a1, b0.z, b0.w);
    mma16h(dh[1][2], a1, b1.x, b1.y);  mma16h(dh[1][3], a1, b1.z, b1.w);
    mma16h(dh[1][4], a1, b2.x, b2.y);  mma16h(dh[1][5], a1, b2.z, b2.w);
    mma16h(dh[1][6], a1, b3.x, b3.y);  mma16h(dh[1][7], a1, b3.z, b3.w);
}

__device__ __forceinline__ void ins5(float (&t)[5], float v) {
    if (v > t[0]) {
        t[0] = v;
        if (t[0] > t[1]) { float x = t[1]; t[1] = t[0]; t[0] = x;
            if (t[1] > t[2]) { x = t[2]; t[2] = t[1]; t[1] = x;
                if (t[2] > t[3]) { x = t[3]; t[3] = t[2]; t[2] = x;
                    if (t[3] > t[4]) { x = t[4]; t[4] = t[3]; t[3] = x; } } } }
    }
}

__device__ __forceinline__ uint32_t pack_h2(float v0, float v1) {
    __half2 h = __floats2half2_rn(v0, v1);   // .x (low) = v0
    return *(uint32_t*)&h;
}

// ---------------------------------------------------------------------------
// Kernel 1: per-(bw,c) support sums. One warp per (bw,c). grid=3200, block=256.
// ---------------------------------------------------------------------------
__global__ void prep_shot_sums(const float* __restrict__ xs) {
    int gw = blockIdx.x * 8 + (threadIdx.x >> 5);
    int lane = threadIdx.x & 31;
    int bw = gw / C_;
    int c = gw - bw * C_;
    const float* base = xs + (size_t)bw * (S_ * C_ * HW_);
    float ss = 0.f, sm = 0.f;
    for (int j = lane; j < S_ * HW_; j += 32) {
        int s = j / HW_;
        int p = j - s * HW_;
        float v = base[((size_t)s * C_ + c) * HW_ + p];
        ss += v * v;
        sm += v;
    }
    ss = warpSum(ss);
    sm = warpSum(sm);
    if (lane == 0) {
        g_sup_inv[bw * C_ + c] = rsqrtf(ss);
        g_proto[bw * C_ + c] = sm * (1.0f / (S_ * HW_));
    }
}

// Kernel: normalize prototypes. grid=40, block=256.
__global__ void prep_proto_norm() {
    int bw = blockIdx.x;
    int tid = threadIdx.x;
    float local = 0.f;
    for (int c = tid; c < C_; c += 256) {
        float v = g_proto[bw * C_ + c];
        local += v * v;
    }
    local = warpSum(local);
    __shared__ float part[8];
    if ((tid & 31) == 0) part[tid >> 5] = local;
    __syncthreads();
    __shared__ float sinv;
    if (tid == 0) {
        float t = 0.f;
        #pragma unroll
        for (int k = 0; k < 8; k++) t += part[k];
        sinv = rsqrtf(t);
    }
    __syncthreads();
    for (int c = tid; c < C_; c += 256)
        g_pn[bw * C_ + c] = g_proto[bw * C_ + c] * sinv;
}

// ---------------------------------------------------------------------------
// Kernel 2: pack A SINGLE PASS (unscaled fp16 fragments) + query stats
// (qn, qd_inv). grid = B*Q = 600, block = 256. One sweep of x_query.
// ---------------------------------------------------------------------------
#define CCH 64
__global__ void __launch_bounds__(256) packA(const float* __restrict__ xq) {
    int bq = blockIdx.x;
    int b = bq / Q_;
    int q = bq - b * Q_;
    int tid = threadIdx.x;
    const float* src = xq + (size_t)bq * (C_ * HW_);

    __shared__ float s_t[CCH][101];
    __shared__ float csum[C_];
    __shared__ float persq[HW_];
    __shared__ float part[8];
    __shared__ float sinv;

    if (tid < HW_) persq[tid] = 0.f;
    __syncthreads();

    for (int cc0 = 0; cc0 < C_; cc0 += CCH) {
        for (int idx = tid; idx < CCH * HW_; idx += 256) {
            int cc = idx / HW_;
            int p = idx - cc * HW_;
            s_t[cc][p] = src[(size_t)(cc0 + cc) * HW_ + p];
        }
        __syncthreads();

        // per-channel sums (each channel fully inside this chunk)
        int wid = tid >> 5, lane = tid & 31;
        for (int cc = wid; cc < CCH; cc += 8) {
            float sm = 0.f;
            #pragma unroll
            for (int pp = lane; pp < HW_; pp += 32) sm += s_t[cc][pp];
            sm = warpSum(sm);
            if (lane == 0) csum[cc0 + cc] = sm;
        }
        // per-position square sums (accumulate across chunks)
        if (tid < HW_) {
            float acc = 0.f;
            #pragma unroll 8
            for (int cc = 0; cc < CCH; cc++) {
                float v = s_t[cc][tid];
                acc += v * v;
            }
            persq[tid] += acc;
        }
        // write fp16 pairs (UNSCALED) in fragment order
        for (int idx = tid; idx < (CCH / 2) * HW_; idx += 256) {
            int cc2 = idx & 31;
            int p = idx >> 5;
            int c = cc0 + cc2 * 2;        // even channel of the pair
            int k16 = c >> 4;
            int c16 = c & 15;             // even
            int r = q * HW_ + p;
            int mt = r >> 7;
            int rl = r & 127;
            int mg = rl >> 4;
            int rr = rl & 15;
            int tig = (c16 & 7) >> 1;
            int reg = (rr >> 3) | ((c16 >> 3) << 1);
            int lane2 = ((rr & 7) << 2) | tig;
            size_t tile = ((size_t)(b * MT_ + mt) * K16_ + k16) * 8 + mg;
            g_A[tile * 128 + lane2 * 4 + reg] = pack_h2(s_t[cc2 * 2][p], s_t[cc2 * 2 + 1][p]);
        }
        __syncthreads();
    }

    if (tid < HW_)
        g_qd_inv[(size_t)b * MROWS_ + q * HW_ + tid] = rsqrtf(persq[tid]);

    // qn = normalize_c(mean_p)
    float local = 0.f;
    for (int c = tid; c < C_; c += 256) {
        float m = csum[c] * (1.0f / HW_);
        local += m * m;
    }
    local = warpSum(local);
    if ((tid & 31) == 0) part[tid >> 5] = local;
    __syncthreads();
    if (tid == 0) {
        float t = 0.f;
        #pragma unroll
        for (int k = 0; k < 8; k++) t += part[k];
        sinv = rsqrtf(t);
    }
    __syncthreads();
    for (int c = tid; c < C_; c += 256)
        g_qn[bq * C_ + c] = csum[c] * (1.0f / HW_) * sinv;
}

// ---------------------------------------------------------------------------
// Kernel 3: pack B (support descriptors, scaled, fp16, fragment order).
// grid = B*W*S = 200, block = 256.
// ---------------------------------------------------------------------------
__global__ void __launch_bounds__(256) packB(const float* __restrict__ xs) {
    int bws = blockIdx.x;
    int s = bws % S_;
    int bw = bws / S_;
    int tid = threadIdx.x;
    const float* src = xs + (size_t)(bw * S_ + s) * (C_ * HW_);

    __shared__ float s_t[CCH][101];

    for (int cc0 = 0; cc0 < C_; cc0 += CCH) {
        __syncthreads();
        for (int idx = tid; idx < CCH * HW_; idx += 256) {
            int cc = idx / HW_;
            int p = idx - cc * HW_;
            s_t[cc][p] = src[(size_t)(cc0 + cc) * HW_ + p];
        }
        __syncthreads();
        for (int idx = tid; idx < (CCH / 2) * HW_; idx += 256) {
            int cc2 = idx & 31;
            int p = idx >> 5;
            int c = cc0 + cc2 * 2;
            int k16 = c >> 4;
            int c16 = c & 15;
            int d = s * HW_ + p;          // 0..499
            int n16 = d >> 4;
            int nsub = (d >> 3) & 1;
            int nl = d & 7;
            int tig = (c16 & 7) >> 1;
            int reg = c16 >> 3;
            int lane = (nl << 2) | tig;
            float v0 = s_t[cc2 * 2][p] * g_sup_inv[bw * C_ + c];
            float v1 = s_t[cc2 * 2 + 1][p] * g_sup_inv[bw * C_ + c + 1];
            size_t tile = ((size_t)bw * K16_ + k16) * 32 + n16;
            g_Bm[tile * 128 + lane * 4 + nsub * 2 + reg] = pack_h2(v0, v1);
        }
    }
}

// ---------------------------------------------------------------------------
// Kernel 4: mma.sync fp16 GEMM (fp16 acc, fp32 promote every 8 K-steps)
// with register double-buffered prefetch. grid=(59,40), block=256.
// 8 warps: 4(M) x 2(N). CTA tile M=128, N=512 in 4 chunks of 128, K=640.
// Epilogue applies qd_inv to the per-row top-5 sum (rank-invariant).
// ---------------------------------------------------------------------------
__global__ void __launch_bounds__(256) gemm_topk() {
    int mt = blockIdx.x;
    int bw = blockIdx.y;
    int b = bw / W_;
    int tid = threadIdx.x;
    int lane = tid & 31;
    int wid = tid >> 5;
    int wm = wid & 3;
    int wn = wid >> 2;

    const uint4* Ab = (const uint4*)g_A + (size_t)(b * MT_ + mt) * (K16_ * 8 * 32);
    const uint4* Bb = (const uint4*)g_Bm + (size_t)bw * (K16_ * 32 * 32);

    float t5[4][5];
    #pragma unroll
    for (int i = 0; i < 4; i++)
        #pragma unroll
        for (int s = 0; s < 5; s++) t5[i][s] = -1e30f;

    #pragma unroll 1
    for (int nc = 0; nc < 4; nc++) {
        float d[2][8][4];
        #pragma unroll
        for (int i = 0; i < 2; i++)
            #pragma unroll
            for (int j = 0; j < 8; j++)
                #pragma unroll
                for (int e = 0; e < 4; e++) d[i][j][e] = 0.f;

        uint32_t dh[2][8][2];
        int nb0 = nc * 8 + wn * 4;        // pair-tile index base

        // prologue: load k=0 fragments
        uint4 a0 = Ab[((0 * 8 + wm * 2 + 0) << 5) + lane];
        uint4 a1 = Ab[((0 * 8 + wm * 2 + 1) << 5) + lane];
        uint4 b0 = Bb[(((0 << 5) + nb0 + 0) << 5) + lane];
        uint4 b1 = Bb[(((0 << 5) + nb0 + 1) << 5) + lane];
        uint4 b2 = Bb[(((0 << 5) + nb0 + 2) << 5) + lane];
        uint4 b3 = Bb[(((0 << 5) + nb0 + 3) << 5) + lane];

        #pragma unroll 1
        for (int k = 0; k < K16_ - 1; k++) {
            // prefetch k+1 into shadow registers (lands during the MMA block)
            int kn = k + 1;
            uint4 na0 = Ab[((kn * 8 + wm * 2 + 0) << 5) + lane];
            uint4 na1 = Ab[((kn * 8 + wm * 2 + 1) << 5) + lane];
            uint4 nb0v = Bb[(((kn << 5) + nb0 + 0) << 5) + lane];
            uint4 nb1v = Bb[(((kn << 5) + nb0 + 1) << 5) + lane];
            uint4 nb2v = Bb[(((kn << 5) + nb0 + 2) << 5) + lane];
            uint4 nb3v = Bb[(((kn << 5) + nb0 + 3) << 5) + lane];

            if ((k & 7) == 0) {
                #pragma unroll
                for (int i = 0; i < 2; i++)
                    #pragma unroll
                    for (int j = 0; j < 8; j++) { dh[i][j][0] = 0u; dh[i][j][1] = 0u; }
            }

            mma_block(dh, a0, a1, b0, b1, b2, b3);

            if ((k & 7) == 7) {
                #pragma unroll
                for (int i = 0; i < 2; i++)
                    #pragma unroll
                    for (int j = 0; j < 8; j++) {
                        float2 f0 = __half22float2(*(__half2*)&dh[i][j][0]);
                        float2 f1 = __half22float2(*(__half2*)&dh[i][j][1]);
                        d[i][j][0] += f0.x;
                        d[i][j][1] += f0.y;
                        d[i][j][2] += f1.x;
                        d[i][j][3] += f1.y;
                    }
            }

            a0 = na0; a1 = na1;
            b0 = nb0v; b1 = nb1v; b2 = nb2v; b3 = nb3v;
        }

        // final k-step (k = K16_-1; (k & 7)==7 since K16_=40)
        mma_block(dh, a0, a1, b0, b1, b2, b3);
        #pragma unroll
        for (int i = 0; i < 2; i++)
            #pragma unroll
            for (int j = 0; j < 8; j++) {
                float2 f0 = __half22float2(*(__half2*)&dh[i][j][0]);
                float2 f1 = __half22float2(*(__half2*)&dh[i][j][1]);
                d[i][j][0] += f0.x;
                d[i][j][1] += f0.y;
                d[i][j][2] += f1.x;
                d[i][j][3] += f1.y;
            }

        // fold this n-chunk into per-thread top-5 (rows: i*2+h)
        int cbase = nc * 128 + wn * 64 + (lane & 3) * 2;
        #pragma unroll
        for (int i = 0; i < 2; i++)
            #pragma unroll
            for (int h = 0; h < 2; h++)
                #pragma unroll
                for (int j = 0; j < 8; j++)
                    #pragma unroll
                    for (int e = 0; e < 2; e++) {
                        int c = cbase + j * 8 + e;
                        float v = d[i][j][h * 2 + e];
                        if (c < 500) ins5(t5[i * 2 + h], v);
                    }
    }

    // merge per-row top-5 candidates via smem
    __shared__ float s5[128][42];
    int owner = wn * 4 + (lane & 3);   // 0..7
    #pragma unroll
    for (int i = 0; i < 2; i++)
        #pragma unroll
        for (int h = 0; h < 2; h++) {
            int rl = wm * 32 + i * 16 + h * 8 + (lane >> 2);
            #pragma unroll
            for (int s = 0; s < 5; s++)
                s5[rl][owner * 5 + s] = t5[i * 2 + h][s];
        }
    __syncthreads();

    if (tid < 128) {
        float t[5] = {-1e30f, -1e30f, -1e30f, -1e30f, -1e30f};
        #pragma unroll
        for (int s = 0; s < 40; s++) ins5(t, s5[tid][s]);
        int r = mt * 128 + tid;
        if (r < MROWS_) {
            float qi = g_qd_inv[(size_t)b * MROWS_ + r];
            g_rowsum[(size_t)bw * MROWS_ + r] =
                (t[0] + t[1] + t[2] + t[3] + t[4]) * qi;
        }
    }
}

// ---------------------------------------------------------------------------
// Kernel 5: finalize. grid = B*Q*W = 3000, block = 128.
// ---------------------------------------------------------------------------
__global__ void finalize(const float* __restrict__ r_cos, const float* __restrict__ r_dn4,
                         float* __restrict__ out) {
    int idx = blockIdx.x;
    int w = idx % W_;
    int q = (idx / W_) % Q_;
    int b = idx / (W_ * Q_);
    int tid = threadIdx.x;
    int bw = b * W_ + w;
    int bq = b * Q_ + q;

    float cosd = 0.f;
    for (int c = tid; c < C_; c += 128)
        cosd += g_qn[bq * C_ + c] * g_pn[bw * C_ + c];
    float dn4 = 0.f;
    if (tid < HW_)
        dn4 = g_rowsum[(size_t)bw * MROWS_ + q * HW_ + tid];

    cosd = warpSum(cosd);
    dn4 = warpSum(dn4);
    __shared__ float pc[4], pd[4];
    if ((tid & 31) == 0) { pc[tid >> 5] = cosd; pd[tid >> 5] = dn4; }
    __syncthreads();
    if (tid == 0) {
        float c2 = pc[0] + pc[1] + pc[2] + pc[3];
        float a = pd[0] + pd[1] + pd[2] + pd[3];
        out[idx] = r_cos[0] * c2 + r_dn4[0] * (a * (1.0f / NK_));
    }
}

// ---------------------------------------------------------------------------
// Launch order puts gemm_topk 4th (the ncu capture window) — dependency-safe:
// prep_proto_norm is only needed by finalize.
// ---------------------------------------------------------------------------
extern "C" void kernel_launch(void* const* d_in, const int* in_sizes, int n_in,
                              void* d_out, int out_size) {
    const float* x_shot  = (const float*)d_in[0];
    const float* x_query = (const float*)d_in[1];
    const float* r_cos   = (const float*)d_in[2];
    const float* r_dn4   = (const float*)d_in[3];
    float* out = (float*)d_out;

    prep_shot_sums<<<3200, 256>>>(x_shot);
    packA<<<B_ * Q_, 256>>>(x_query);
    packB<<<B_ * W_ * S_, 256>>>(x_shot);
    gemm_topk<<<dim3(MT_, B_ * W_), 256>>>();
    prep_proto_norm<<<40, 256>>>();
    finalize<<<B_ * Q_ * W_, 128>>>(r_cos, r_dn4, out);
}

// round 10
// speedup vs baseline: 1.2849x; 1.1614x over previous
#include <cuda_runtime.h>
#include <cuda_fp16.h>
#include <cstdint>

// Problem constants
#define B_ 8
#define W_ 5
#define S_ 5
#define C_ 640
#define HW_ 100
#define Q_ 75
#define NK_ 5

#define MT_ 59            // M-tiles of 128 over 7500 rows (padded to 7552)
#define MROWS_ 7500
#define K16_ 40           // K steps of 16 (C=640)

// ---------------------------------------------------------------------------
// Scratch (zero-init; pad regions never written -> zeros).
// A: [b][mt][k16][mg(8)] 16x16 fp16 tiles in m16n8k16 A-fragment order
//    (UNSCALED; qd_inv applied in GEMM epilogue — rank-invariant).
// B: [bw][k16][n16(32)] paired 16x8 fp16 tiles (scaled by sup_inv).
// ---------------------------------------------------------------------------
__device__ uint32_t g_A[B_ * MT_ * K16_ * 8 * 128];    // 77.3 MB
__device__ uint32_t g_Bm[B_ * W_ * K16_ * 32 * 128];   // 26.2 MB
__device__ float g_rowsum[B_ * W_ * MROWS_];
__device__ float g_sup_inv[B_ * W_ * C_];
__device__ float g_proto[B_ * W_ * C_];
__device__ float g_pn[B_ * W_ * C_];
__device__ float g_qn[B_ * Q_ * C_];
__device__ float g_qd_inv[B_ * MROWS_];                // [b][q*100+p]

__device__ __forceinline__ float warpSum(float v) {
    #pragma unroll
    for (int o = 16; o; o >>= 1) v += __shfl_xor_sync(0xffffffffu, v, o);
    return v;
}

// fp16-accumulate HMMA
__device__ __forceinline__ void mma16h(uint32_t* d, uint4 a, uint32_t b0, uint32_t b1) {
    asm volatile(
        "mma.sync.aligned.m16n8k16.row.col.f16.f16.f16.f16 "
        "{%0,%1}, {%2,%3,%4,%5}, {%6,%7}, {%0,%1};"
        : "+r"(d[0]), "+r"(d[1])
        : "r"(a.x), "r"(a.y), "r"(a.z), "r"(a.w), "r"(b0), "r"(b1));
}

__device__ __forceinline__ void mma_block(uint32_t dh[2][4][2],
                                          uint4 a0, uint4 a1,
                                          uint4 b0, uint4 b1) {
    mma16h(dh[0][0], a0, b0.x, b0.y);  mma16h(dh[0][1], a0, b0.z, b0.w);
    mma16h(dh[0][2], a0, b1.x, b1.y);  mma16h(dh[0][3], a0, b1.z, b1.w);
    mma16h(dh[1][0], a1, b0.x, b0.y);  mma16h(dh[1][1], a1, b0.z, b0.w);
    mma16h(dh[1][2], a1, b1.x, b1.y);  mma16h(dh[1][3], a1, b1.z, b1.w);
}

__device__ __forceinline__ void ins5(float (&t)[5], float v) {
    if (v > t[0]) {
        t[0] = v;
        if (t[0] > t[1]) { float x = t[1]; t[1] = t[0]; t[0] = x;
            if (t[1] > t[2]) { x = t[2]; t[2] = t[1]; t[1] = x;
                if (t[2] > t[3]) { x = t[3]; t[3] = t[2]; t[2] = x;
                    if (t[3] > t[4]) { x = t[4]; t[4] = t[3]; t[3] = x; } } } }
    }
}

__device__ __forceinline__ uint32_t pack_h2(float v0, float v1) {
    __half2 h = __floats2half2_rn(v0, v1);   // .x (low) = v0
    return *(uint32_t*)&h;
}

// ---------------------------------------------------------------------------
// Kernel 1: per-(bw,c) support sums. One warp per (bw,c). grid=3200, block=256.
// ---------------------------------------------------------------------------
__global__ void prep_shot_sums(const float* __restrict__ xs) {
    int gw = blockIdx.x * 8 + (threadIdx.x >> 5);
    int lane = threadIdx.x & 31;
    int bw = gw / C_;
    int c = gw - bw * C_;
    const float* base = xs + (size_t)bw * (S_ * C_ * HW_);
    float ss = 0.f, sm = 0.f;
    for (int j = lane; j < S_ * HW_; j += 32) {
        int s = j / HW_;
        int p = j - s * HW_;
        float v = base[((size_t)s * C_ + c) * HW_ + p];
        ss += v * v;
        sm += v;
    }
    ss = warpSum(ss);
    sm = warpSum(sm);
    if (lane == 0) {
        g_sup_inv[bw * C_ + c] = rsqrtf(ss);
        g_proto[bw * C_ + c] = sm * (1.0f / (S_ * HW_));
    }
}

// Kernel: normalize prototypes. grid=40, block=256.
__global__ void prep_proto_norm() {
    int bw = blockIdx.x;
    int tid = threadIdx.x;
    float local = 0.f;
    for (int c = tid; c < C_; c += 256) {
        float v = g_proto[bw * C_ + c];
        local += v * v;
    }
    local = warpSum(local);
    __shared__ float part[8];
    if ((tid & 31) == 0) part[tid >> 5] = local;
    __syncthreads();
    __shared__ float sinv;
    if (tid == 0) {
        float t = 0.f;
        #pragma unroll
        for (int k = 0; k < 8; k++) t += part[k];
        sinv = rsqrtf(t);
    }
    __syncthreads();
    for (int c = tid; c < C_; c += 256)
        g_pn[bw * C_ + c] = g_proto[bw * C_ + c] * sinv;
}

// ---------------------------------------------------------------------------
// Kernel 2: pack A SINGLE PASS (unscaled fp16 fragments) + query stats
// (qn, qd_inv). grid = B*Q = 600, block = 256. One sweep of x_query.
// ---------------------------------------------------------------------------
#define CCH 64
__global__ void __launch_bounds__(256) packA(const float* __restrict__ xq) {
    int bq = blockIdx.x;
    int b = bq / Q_;
    int q = bq - b * Q_;
    int tid = threadIdx.x;
    const float* src = xq + (size_t)bq * (C_ * HW_);

    __shared__ float s_t[CCH][101];
    __shared__ float csum[C_];
    __shared__ float persq[HW_];
    __shared__ float part[8];
    __shared__ float sinv;

    if (tid < HW_) persq[tid] = 0.f;
    __syncthreads();

    for (int cc0 = 0; cc0 < C_; cc0 += CCH) {
        for (int idx = tid; idx < CCH * HW_; idx += 256) {
            int cc = idx / HW_;
            int p = idx - cc * HW_;
            s_t[cc][p] = src[(size_t)(cc0 + cc) * HW_ + p];
        }
        __syncthreads();

        int wid = tid >> 5, lane = tid & 31;
        for (int cc = wid; cc < CCH; cc += 8) {
            float sm = 0.f;
            #pragma unroll
            for (int pp = lane; pp < HW_; pp += 32) sm += s_t[cc][pp];
            sm = warpSum(sm);
            if (lane == 0) csum[cc0 + cc] = sm;
        }
        if (tid < HW_) {
            float acc = 0.f;
            #pragma unroll 8
            for (int cc = 0; cc < CCH; cc++) {
                float v = s_t[cc][tid];
                acc += v * v;
            }
            persq[tid] += acc;
        }
        for (int idx = tid; idx < (CCH / 2) * HW_; idx += 256) {
            int cc2 = idx & 31;
            int p = idx >> 5;
            int c = cc0 + cc2 * 2;        // even channel of the pair
            int k16 = c >> 4;
            int c16 = c & 15;             // even
            int r = q * HW_ + p;
            int mt = r >> 7;
            int rl = r & 127;
            int mg = rl >> 4;
            int rr = rl & 15;
            int tig = (c16 & 7) >> 1;
            int reg = (rr >> 3) | ((c16 >> 3) << 1);
            int lane2 = ((rr & 7) << 2) | tig;
            size_t tile = ((size_t)(b * MT_ + mt) * K16_ + k16) * 8 + mg;
            g_A[tile * 128 + lane2 * 4 + reg] = pack_h2(s_t[cc2 * 2][p], s_t[cc2 * 2 + 1][p]);
        }
        __syncthreads();
    }

    if (tid < HW_)
        g_qd_inv[(size_t)b * MROWS_ + q * HW_ + tid] = rsqrtf(persq[tid]);

    float local = 0.f;
    for (int c = tid; c < C_; c += 256) {
        float m = csum[c] * (1.0f / HW_);
        local += m * m;
    }
    local = warpSum(local);
    if ((tid & 31) == 0) part[tid >> 5] = local;
    __syncthreads();
    if (tid == 0) {
        float t = 0.f;
        #pragma unroll
        for (int k = 0; k < 8; k++) t += part[k];
        sinv = rsqrtf(t);
    }
    __syncthreads();
    for (int c = tid; c < C_; c += 256)
        g_qn[bq * C_ + c] = csum[c] * (1.0f / HW_) * sinv;
}

// ---------------------------------------------------------------------------
// Kernel 3: pack B (support descriptors, scaled, fp16, fragment order).
// grid = B*W*S = 200, block = 256.
// ---------------------------------------------------------------------------
__global__ void __launch_bounds__(256) packB(const float* __restrict__ xs) {
    int bws = blockIdx.x;
    int s = bws % S_;
    int bw = bws / S_;
    int tid = threadIdx.x;
    const float* src = xs + (size_t)(bw * S_ + s) * (C_ * HW_);

    __shared__ float s_t[CCH][101];

    for (int cc0 = 0; cc0 < C_; cc0 += CCH) {
        __syncthreads();
        for (int idx = tid; idx < CCH * HW_; idx += 256) {
            int cc = idx / HW_;
            int p = idx - cc * HW_;
            s_t[cc][p] = src[(size_t)(cc0 + cc) * HW_ + p];
        }
        __syncthreads();
        for (int idx = tid; idx < (CCH / 2) * HW_; idx += 256) {
            int cc2 = idx & 31;
            int p = idx >> 5;
            int c = cc0 + cc2 * 2;
            int k16 = c >> 4;
            int c16 = c & 15;
            int d = s * HW_ + p;          // 0..499
            int n16 = d >> 4;
            int nsub = (d >> 3) & 1;
            int nl = d & 7;
            int tig = (c16 & 7) >> 1;
            int reg = c16 >> 3;
            int lane = (nl << 2) | tig;
            float v0 = s_t[cc2 * 2][p] * g_sup_inv[bw * C_ + c];
            float v1 = s_t[cc2 * 2 + 1][p] * g_sup_inv[bw * C_ + c + 1];
            size_t tile = ((size_t)bw * K16_ + k16) * 32 + n16;
            g_Bm[tile * 128 + lane * 4 + nsub * 2 + reg] = pack_h2(v0, v1);
        }
    }
}

// ---------------------------------------------------------------------------
// Kernel 4: mma.sync fp16 GEMM (fp16 acc, fp32 promote every 8 K-steps),
// register prefetch, 2 CTAs/SM (reg cap 128). grid=(59,40), block=256.
// 8 warps: 4(M) x 2(N). CTA tile M=128, N=512 in 8 chunks of 64, K=640.
// Per warp per k-step: 2 A frags + 2 B pair-tiles (32 cols).
// ---------------------------------------------------------------------------
__global__ void __launch_bounds__(256, 2) gemm_topk() {
    int mt = blockIdx.x;
    int bw = blockIdx.y;
    int b = bw / W_;
    int tid = threadIdx.x;
    int lane = tid & 31;
    int wid = tid >> 5;
    int wm = wid & 3;
    int wn = wid >> 2;

    const uint4* Ab = (const uint4*)g_A + (size_t)(b * MT_ + mt) * (K16_ * 8 * 32);
    const uint4* Bb = (const uint4*)g_Bm + (size_t)bw * (K16_ * 32 * 32);

    float t5[4][5];
    #pragma unroll
    for (int i = 0; i < 4; i++)
        #pragma unroll
        for (int s = 0; s < 5; s++) t5[i][s] = -1e30f;

    #pragma unroll 1
    for (int nc = 0; nc < 8; nc++) {
        float d[2][4][4];
        #pragma unroll
        for (int i = 0; i < 2; i++)
            #pragma unroll
            for (int j = 0; j < 4; j++)
                #pragma unroll
                for (int e = 0; e < 4; e++) d[i][j][e] = 0.f;

        uint32_t dh[2][4][2];
        int nb0 = nc * 4 + wn * 2;        // pair-tile index base (2 per warp)

        // prologue: load k=0 fragments
        uint4 a0 = Ab[((0 * 8 + wm * 2 + 0) << 5) + lane];
        uint4 a1 = Ab[((0 * 8 + wm * 2 + 1) << 5) + lane];
        uint4 b0 = Bb[(((0 << 5) + nb0 + 0) << 5) + lane];
        uint4 b1 = Bb[(((0 << 5) + nb0 + 1) << 5) + lane];

        #pragma unroll 1
        for (int k = 0; k < K16_ - 1; k++) {
            int kn = k + 1;
            uint4 na0 = Ab[((kn * 8 + wm * 2 + 0) << 5) + lane];
            uint4 na1 = Ab[((kn * 8 + wm * 2 + 1) << 5) + lane];
            uint4 nb0v = Bb[(((kn << 5) + nb0 + 0) << 5) + lane];
            uint4 nb1v = Bb[(((kn << 5) + nb0 + 1) << 5) + lane];

            if ((k & 7) == 0) {
                #pragma unroll
                for (int i = 0; i < 2; i++)
                    #pragma unroll
                    for (int j = 0; j < 4; j++) { dh[i][j][0] = 0u; dh[i][j][1] = 0u; }
            }

            mma_block(dh, a0, a1, b0, b1);

            if ((k & 7) == 7) {
                #pragma unroll
                for (int i = 0; i < 2; i++)
                    #pragma unroll
                    for (int j = 0; j < 4; j++) {
                        float2 f0 = __half22float2(*(__half2*)&dh[i][j][0]);
                        float2 f1 = __half22float2(*(__half2*)&dh[i][j][1]);
                        d[i][j][0] += f0.x;
                        d[i][j][1] += f0.y;
                        d[i][j][2] += f1.x;
                        d[i][j][3] += f1.y;
                    }
            }

            a0 = na0; a1 = na1;
            b0 = nb0v; b1 = nb1v;
        }

        // final k-step (k = K16_-1; (k & 7)==7 since K16_=40)
        mma_block(dh, a0, a1, b0, b1);
        #pragma unroll
        for (int i = 0; i < 2; i++)
            #pragma unroll
            for (int j = 0; j < 4; j++) {
                float2 f0 = __half22float2(*(__half2*)&dh[i][j][0]);
                float2 f1 = __half22float2(*(__half2*)&dh[i][j][1]);
                d[i][j][0] += f0.x;
                d[i][j][1] += f0.y;
                d[i][j][2] += f1.x;
                d[i][j][3] += f1.y;
            }

        // fold this 64-col chunk into per-thread top-5 (rows: i*2+h)
        int cbase = nc * 64 + wn * 32 + (lane & 3) * 2;
        #pragma unroll
        for (int i = 0; i < 2; i++)
            #pragma unroll
            for (int h = 0; h < 2; h++)
                #pragma unroll
                for (int j = 0; j < 4; j++)
                    #pragma unroll
                    for (int e = 0; e < 2; e++) {
                        int c = cbase + j * 8 + e;
                        float v = d[i][j][h * 2 + e];
                        if (c < 500) ins5(t5[i * 2 + h], v);
                    }
    }

    // merge per-row top-5 candidates via smem (8 owners x 5 per row)
    __shared__ float s5[128][42];
    int owner = wn * 4 + (lane & 3);   // 0..7
    #pragma unroll
    for (int i = 0; i < 2; i++)
        #pragma unroll
        for (int h = 0; h < 2; h++) {
            int rl = wm * 32 + i * 16 + h * 8 + (lane >> 2);
            #pragma unroll
            for (int s = 0; s < 5; s++)
                s5[rl][owner * 5 + s] = t5[i * 2 + h][s];
        }
    __syncthreads();

    if (tid < 128) {
        float t[5] = {-1e30f, -1e30f, -1e30f, -1e30f, -1e30f};
        #pragma unroll
        for (int s = 0; s < 40; s++) ins5(t, s5[tid][s]);
        int r = mt * 128 + tid;
        if (r < MROWS_) {
            float qi = g_qd_inv[(size_t)b * MROWS_ + r];
            g_rowsum[(size_t)bw * MROWS_ + r] =
                (t[0] + t[1] + t[2] + t[3] + t[4]) * qi;
        }
    }
}

// ---------------------------------------------------------------------------
// Kernel 5: finalize. grid = B*Q*W = 3000, block = 128.
// ---------------------------------------------------------------------------
__global__ void finalize(const float* __restrict__ r_cos, const float* __restrict__ r_dn4,
                         float* __restrict__ out) {
    int idx = blockIdx.x;
    int w = idx % W_;
    int q = (idx / W_) % Q_;
    int b = idx / (W_ * Q_);
    int tid = threadIdx.x;
    int bw = b * W_ + w;
    int bq = b * Q_ + q;

    float cosd = 0.f;
    for (int c = tid; c < C_; c += 128)
        cosd += g_qn[bq * C_ + c] * g_pn[bw * C_ + c];
    float dn4 = 0.f;
    if (tid < HW_)
        dn4 = g_rowsum[(size_t)bw * MROWS_ + q * HW_ + tid];

    cosd = warpSum(cosd);
    dn4 = warpSum(dn4);
    __shared__ float pc[4], pd[4];
    if ((tid & 31) == 0) { pc[tid >> 5] = cosd; pd[tid >> 5] = dn4; }
    __syncthreads();
    if (tid == 0) {
        float c2 = pc[0] + pc[1] + pc[2] + pc[3];
        float a = pd[0] + pd[1] + pd[2] + pd[3];
        out[idx] = r_cos[0] * c2 + r_dn4[0] * (a * (1.0f / NK_));
    }
}

// ---------------------------------------------------------------------------
// gemm_topk stays 4th launch (ncu capture window).
// ---------------------------------------------------------------------------
extern "C" void kernel_launch(void* const* d_in, const int* in_sizes, int n_in,
                              void* d_out, int out_size) {
    const float* x_shot  = (const float*)d_in[0];
    const float* x_query = (const float*)d_in[1];
    const float* r_cos   = (const float*)d_in[2];
    const float* r_dn4   = (const float*)d_in[3];
    float* out = (float*)d_out;

    prep_shot_sums<<<3200, 256>>>(x_shot);
    packA<<<B_ * Q_, 256>>>(x_query);
    packB<<<B_ * W_ * S_, 256>>>(x_shot);
    gemm_topk<<<dim3(MT_, B_ * W_), 256>>>();
    prep_proto_norm<<<40, 256>>>();
    finalize<<<B_ * Q_ * W_, 128>>>(r_cos, r_dn4, out);
}

// round 11
// speedup vs baseline: 1.6597x; 1.2916x over previous
#include <cuda_runtime.h>
#include <cuda_fp16.h>
#include <cstdint>

// Problem constants
#define B_ 8
#define W_ 5
#define S_ 5
#define C_ 640
#define HW_ 100
#define Q_ 75
#define NK_ 5

#define MT_ 59            // M-tiles of 128 over 7500 rows (padded to 7552)
#define MROWS_ 7500
#define K16_ 40           // K steps of 16 (C=640)

// ---------------------------------------------------------------------------
// Scratch (zero-init; pad regions never written -> zeros).
// A: [b][mt][k16][mg(8)] 16x16 fp16 tiles in m16n8k16 A-fragment order
//    (UNSCALED; qd_inv applied in GEMM epilogue — rank-invariant).
// B: [bw][k16][n16(32)] paired 16x8 fp16 tiles (scaled by sup_inv).
// ---------------------------------------------------------------------------
__device__ uint32_t g_A[B_ * MT_ * K16_ * 8 * 128];    // 77.3 MB
__device__ uint32_t g_Bm[B_ * W_ * K16_ * 32 * 128];   // 26.2 MB
__device__ float g_rowsum[B_ * W_ * MROWS_];
__device__ float g_sup_inv[B_ * W_ * C_];
__device__ float g_proto[B_ * W_ * C_];
__device__ float g_pn[B_ * W_ * C_];
__device__ float g_qn[B_ * Q_ * C_];
__device__ float g_qd_inv[B_ * MROWS_];                // [b][q*100+p]

__device__ __forceinline__ float warpSum(float v) {
    #pragma unroll
    for (int o = 16; o; o >>= 1) v += __shfl_xor_sync(0xffffffffu, v, o);
    return v;
}

// fp16-accumulate HMMA
__device__ __forceinline__ void mma16h(uint32_t* d, uint4 a, uint32_t b0, uint32_t b1) {
    asm volatile(
        "mma.sync.aligned.m16n8k16.row.col.f16.f16.f16.f16 "
        "{%0,%1}, {%2,%3,%4,%5}, {%6,%7}, {%0,%1};"
        : "+r"(d[0]), "+r"(d[1])
        : "r"(a.x), "r"(a.y), "r"(a.z), "r"(a.w), "r"(b0), "r"(b1));
}

__device__ __forceinline__ void mma_block(uint32_t dh[2][4][2],
                                          uint4 a0, uint4 a1,
                                          uint4 b0, uint4 b1) {
    mma16h(dh[0][0], a0, b0.x, b0.y);  mma16h(dh[0][1], a0, b0.z, b0.w);
    mma16h(dh[0][2], a0, b1.x, b1.y);  mma16h(dh[0][3], a0, b1.z, b1.w);
    mma16h(dh[1][0], a1, b0.x, b0.y);  mma16h(dh[1][1], a1, b0.z, b0.w);
    mma16h(dh[1][2], a1, b1.x, b1.y);  mma16h(dh[1][3], a1, b1.z, b1.w);
}

__device__ __forceinline__ void ins5(float (&t)[5], float v) {
    if (v > t[0]) {
        t[0] = v;
        if (t[0] > t[1]) { float x = t[1]; t[1] = t[0]; t[0] = x;
            if (t[1] > t[2]) { x = t[2]; t[2] = t[1]; t[1] = x;
                if (t[2] > t[3]) { x = t[3]; t[3] = t[2]; t[2] = x;
                    if (t[3] > t[4]) { x = t[4]; t[4] = t[3]; t[3] = x; } } } }
    }
}

__device__ __forceinline__ uint32_t pack_h2(float v0, float v1) {
    __half2 h = __floats2half2_rn(v0, v1);   // .x (low) = v0
    return *(uint32_t*)&h;
}

// ---------------------------------------------------------------------------
// Kernel 1: per-(bw,c) support sums. One warp per (bw,c). grid=3200, block=256.
// ---------------------------------------------------------------------------
__global__ void prep_shot_sums(const float* __restrict__ xs) {
    int gw = blockIdx.x * 8 + (threadIdx.x >> 5);
    int lane = threadIdx.x & 31;
    int bw = gw / C_;
    int c = gw - bw * C_;
    const float* base = xs + (size_t)bw * (S_ * C_ * HW_);
    float ss = 0.f, sm = 0.f;
    for (int j = lane; j < S_ * HW_; j += 32) {
        int s = j / HW_;
        int p = j - s * HW_;
        float v = base[((size_t)s * C_ + c) * HW_ + p];
        ss += v * v;
        sm += v;
    }
    ss = warpSum(ss);
    sm = warpSum(sm);
    if (lane == 0) {
        g_sup_inv[bw * C_ + c] = rsqrtf(ss);
        g_proto[bw * C_ + c] = sm * (1.0f / (S_ * HW_));
    }
}

// Kernel: normalize prototypes. grid=40, block=256.
__global__ void prep_proto_norm() {
    int bw = blockIdx.x;
    int tid = threadIdx.x;
    float local = 0.f;
    for (int c = tid; c < C_; c += 256) {
        float v = g_proto[bw * C_ + c];
        local += v * v;
    }
    local = warpSum(local);
    __shared__ float part[8];
    if ((tid & 31) == 0) part[tid >> 5] = local;
    __syncthreads();
    __shared__ float sinv;
    if (tid == 0) {
        float t = 0.f;
        #pragma unroll
        for (int k = 0; k < 8; k++) t += part[k];
        sinv = rsqrtf(t);
    }
    __syncthreads();
    for (int c = tid; c < C_; c += 256)
        g_pn[bw * C_ + c] = g_proto[bw * C_ + c] * sinv;
}

// ---------------------------------------------------------------------------
// Kernel 2: pack A SINGLE PASS (unscaled fp16 fragments) + query stats
// (qn, qd_inv). grid = B*Q = 600, block = 256. One sweep of x_query.
// ---------------------------------------------------------------------------
#define CCH 64
__global__ void __launch_bounds__(256) packA(const float* __restrict__ xq) {
    int bq = blockIdx.x;
    int b = bq / Q_;
    int q = bq - b * Q_;
    int tid = threadIdx.x;
    const float* src = xq + (size_t)bq * (C_ * HW_);

    __shared__ float s_t[CCH][101];
    __shared__ float csum[C_];
    __shared__ float persq[HW_];
    __shared__ float part[8];
    __shared__ float sinv;

    if (tid < HW_) persq[tid] = 0.f;
    __syncthreads();

    for (int cc0 = 0; cc0 < C_; cc0 += CCH) {
        for (int idx = tid; idx < CCH * HW_; idx += 256) {
            int cc = idx / HW_;
            int p = idx - cc * HW_;
            s_t[cc][p] = src[(size_t)(cc0 + cc) * HW_ + p];
        }
        __syncthreads();

        int wid = tid >> 5, lane = tid & 31;
        for (int cc = wid; cc < CCH; cc += 8) {
            float sm = 0.f;
            #pragma unroll
            for (int pp = lane; pp < HW_; pp += 32) sm += s_t[cc][pp];
            sm = warpSum(sm);
            if (lane == 0) csum[cc0 + cc] = sm;
        }
        if (tid < HW_) {
            float acc = 0.f;
            #pragma unroll 8
            for (int cc = 0; cc < CCH; cc++) {
                float v = s_t[cc][tid];
                acc += v * v;
            }
            persq[tid] += acc;
        }
        for (int idx = tid; idx < (CCH / 2) * HW_; idx += 256) {
            int cc2 = idx & 31;
            int p = idx >> 5;
            int c = cc0 + cc2 * 2;        // even channel of the pair
            int k16 = c >> 4;
            int c16 = c & 15;             // even
            int r = q * HW_ + p;
            int mt = r >> 7;
            int rl = r & 127;
            int mg = rl >> 4;
            int rr = rl & 15;
            int tig = (c16 & 7) >> 1;
            int reg = (rr >> 3) | ((c16 >> 3) << 1);
            int lane2 = ((rr & 7) << 2) | tig;
            size_t tile = ((size_t)(b * MT_ + mt) * K16_ + k16) * 8 + mg;
            g_A[tile * 128 + lane2 * 4 + reg] = pack_h2(s_t[cc2 * 2][p], s_t[cc2 * 2 + 1][p]);
        }
        __syncthreads();
    }

    if (tid < HW_)
        g_qd_inv[(size_t)b * MROWS_ + q * HW_ + tid] = rsqrtf(persq[tid]);

    float local = 0.f;
    for (int c = tid; c < C_; c += 256) {
        float m = csum[c] * (1.0f / HW_);
        local += m * m;
    }
    local = warpSum(local);
    if ((tid & 31) == 0) part[tid >> 5] = local;
    __syncthreads();
    if (tid == 0) {
        float t = 0.f;
        #pragma unroll
        for (int k = 0; k < 8; k++) t += part[k];
        sinv = rsqrtf(t);
    }
    __syncthreads();
    for (int c = tid; c < C_; c += 256)
        g_qn[bq * C_ + c] = csum[c] * (1.0f / HW_) * sinv;
}

// ---------------------------------------------------------------------------
// Kernel 3: pack B (support descriptors, scaled, fp16, fragment order).
// grid = B*W*S = 200, block = 256.
// ---------------------------------------------------------------------------
__global__ void __launch_bounds__(256) packB(const float* __restrict__ xs) {
    int bws = blockIdx.x;
    int s = bws % S_;
    int bw = bws / S_;
    int tid = threadIdx.x;
    const float* src = xs + (size_t)(bw * S_ + s) * (C_ * HW_);

    __shared__ float s_t[CCH][101];

    for (int cc0 = 0; cc0 < C_; cc0 += CCH) {
        __syncthreads();
        for (int idx = tid; idx < CCH * HW_; idx += 256) {
            int cc = idx / HW_;
            int p = idx - cc * HW_;
            s_t[cc][p] = src[(size_t)(cc0 + cc) * HW_ + p];
        }
        __syncthreads();
        for (int idx = tid; idx < (CCH / 2) * HW_; idx += 256) {
            int cc2 = idx & 31;
            int p = idx >> 5;
            int c = cc0 + cc2 * 2;
            int k16 = c >> 4;
            int c16 = c & 15;
            int d = s * HW_ + p;          // 0..499
            int n16 = d >> 4;
            int nsub = (d >> 3) & 1;
            int nl = d & 7;
            int tig = (c16 & 7) >> 1;
            int reg = c16 >> 3;
            int lane = (nl << 2) | tig;
            float v0 = s_t[cc2 * 2][p] * g_sup_inv[bw * C_ + c];
            float v1 = s_t[cc2 * 2 + 1][p] * g_sup_inv[bw * C_ + c + 1];
            size_t tile = ((size_t)bw * K16_ + k16) * 32 + n16;
            g_Bm[tile * 128 + lane * 4 + nsub * 2 + reg] = pack_h2(v0, v1);
        }
    }
}

// ---------------------------------------------------------------------------
// Kernel 4: mma.sync fp16 GEMM (fp16 acc across all K, no promote),
// pointer-increment addressing, 3 CTAs/SM (reg cap 84). grid=(59,40).
// 8 warps: 4(M) x 2(N). CTA tile M=128, N=512 in 8 chunks of 64, K=640.
// ---------------------------------------------------------------------------
__global__ void __launch_bounds__(256, 3) gemm_topk() {
    int mt = blockIdx.x;
    int bw = blockIdx.y;
    int b = bw / W_;
    int tid = threadIdx.x;
    int lane = tid & 31;
    int wid = tid >> 5;
    int wm = wid & 3;
    int wn = wid >> 2;

    const uint4* Ab = (const uint4*)g_A + (size_t)(b * MT_ + mt) * (K16_ * 8 * 32)
                      + ((wm * 2) << 5) + lane;
    const uint4* Bb = (const uint4*)g_Bm + (size_t)bw * (K16_ * 32 * 32) + lane;

    float t5[4][5];
    #pragma unroll
    for (int i = 0; i < 4; i++)
        #pragma unroll
        for (int s = 0; s < 5; s++) t5[i][s] = -1e30f;

    #pragma unroll 1
    for (int nc = 0; nc < 8; nc++) {
        uint32_t dh[2][4][2];
        #pragma unroll
        for (int i = 0; i < 2; i++)
            #pragma unroll
            for (int j = 0; j < 4; j++) { dh[i][j][0] = 0u; dh[i][j][1] = 0u; }

        int nb0 = nc * 4 + wn * 2;        // pair-tile index base (2 per warp)
        const uint4* ap = Ab;
        const uint4* bp = Bb + (nb0 << 5);

        #pragma unroll 2
        for (int k = 0; k < K16_; k++) {
            uint4 a0 = ap[0];
            uint4 a1 = ap[32];
            uint4 b0 = bp[0];
            uint4 b1 = bp[32];
            ap += 256;       // next k16: 8 tiles * 32 uint4
            bp += 1024;      // next k16: 32 tiles * 32 uint4
            mma_block(dh, a0, a1, b0, b1);
        }

        // fold this 64-col chunk into per-thread top-5 (rows: i*2+h)
        int cbase = nc * 64 + wn * 32 + (lane & 3) * 2;
        #pragma unroll
        for (int i = 0; i < 2; i++)
            #pragma unroll
            for (int h = 0; h < 2; h++)
                #pragma unroll
                for (int j = 0; j < 4; j++) {
                    float2 f = __half22float2(*(__half2*)&dh[i][j][h]);
                    int c = cbase + j * 8;
                    if (c < 500) ins5(t5[i * 2 + h], f.x);
                    if (c + 1 < 500) ins5(t5[i * 2 + h], f.y);
                }
    }

    // merge per-row top-5 candidates via smem (8 owners x 5 per row)
    __shared__ float s5[128][42];
    int owner = wn * 4 + (lane & 3);   // 0..7
    #pragma unroll
    for (int i = 0; i < 2; i++)
        #pragma unroll
        for (int h = 0; h < 2; h++) {
            int rl = wm * 32 + i * 16 + h * 8 + (lane >> 2);
            #pragma unroll
            for (int s = 0; s < 5; s++)
                s5[rl][owner * 5 + s] = t5[i * 2 + h][s];
        }
    __syncthreads();

    if (tid < 128) {
        float t[5] = {-1e30f, -1e30f, -1e30f, -1e30f, -1e30f};
        #pragma unroll
        for (int s = 0; s < 40; s++) ins5(t, s5[tid][s]);
        int r = mt * 128 + tid;
        if (r < MROWS_) {
            float qi = g_qd_inv[(size_t)b * MROWS_ + r];
            g_rowsum[(size_t)bw * MROWS_ + r] =
                (t[0] + t[1] + t[2] + t[3] + t[4]) * qi;
        }
    }
}

// ---------------------------------------------------------------------------
// Kernel 5: finalize. grid = B*Q*W = 3000, block = 128.
// ---------------------------------------------------------------------------
__global__ void finalize(const float* __restrict__ r_cos, const float* __restrict__ r_dn4,
                         float* __restrict__ out) {
    int idx = blockIdx.x;
    int w = idx % W_;
    int q = (idx / W_) % Q_;
    int b = idx / (W_ * Q_);
    int tid = threadIdx.x;
    int bw = b * W_ + w;
    int bq = b * Q_ + q;

    float cosd = 0.f;
    for (int c = tid; c < C_; c += 128)
        cosd += g_qn[bq * C_ + c] * g_pn[bw * C_ + c];
    float dn4 = 0.f;
    if (tid < HW_)
        dn4 = g_rowsum[(size_t)bw * MROWS_ + q * HW_ + tid];

    cosd = warpSum(cosd);
    dn4 = warpSum(dn4);
    __shared__ float pc[4], pd[4];
    if ((tid & 31) == 0) { pc[tid >> 5] = cosd; pd[tid >> 5] = dn4; }
    __syncthreads();
    if (tid == 0) {
        float c2 = pc[0] + pc[1] + pc[2] + pc[3];
        float a = pd[0] + pd[1] + pd[2] + pd[3];
        out[idx] = r_cos[0] * c2 + r_dn4[0] * (a * (1.0f / NK_));
    }
}

// ---------------------------------------------------------------------------
// gemm_topk stays 4th launch (ncu capture window).
// ---------------------------------------------------------------------------
extern "C" void kernel_launch(void* const* d_in, const int* in_sizes, int n_in,
                              void* d_out, int out_size) {
    const float* x_shot  = (const float*)d_in[0];
    const float* x_query = (const float*)d_in[1];
    const float* r_cos   = (const float*)d_in[2];
    const float* r_dn4   = (const float*)d_in[3];
    float* out = (float*)d_out;

    prep_shot_sums<<<3200, 256>>>(x_shot);
    packA<<<B_ * Q_, 256>>>(x_query);
    packB<<<B_ * W_ * S_, 256>>>(x_shot);
    gemm_topk<<<dim3(MT_, B_ * W_), 256>>>();
    prep_proto_norm<<<40, 256>>>();
    finalize<<<B_ * Q_ * W_, 128>>>(r_cos, r_dn4, out);
}

// round 12
// speedup vs baseline: 2.0326x; 1.2247x over previous
#include <cuda_runtime.h>
#include <cuda_fp16.h>
#include <cstdint>

// Problem constants
#define B_ 8
#define W_ 5
#define S_ 5
#define C_ 640
#define HW_ 100
#define Q_ 75
#define NK_ 5

#define MT_ 59            // M-tiles of 128 over 7500 rows (padded to 7552)
#define MROWS_ 7500
#define K16_ 40           // K steps of 16 (C=640)

// ---------------------------------------------------------------------------
// Scratch (zero-init; pad regions never written -> zeros).
// A: [b][mt][k16][mg(8)] 16x16 fp16 tiles in m16n8k16 A-fragment order
//    (UNSCALED; qd_inv applied in GEMM epilogue — rank-invariant).
// B: [bw][k16][n16(32)] paired 16x8 fp16 tiles (scaled by sup_inv).
// ---------------------------------------------------------------------------
__device__ uint32_t g_A[B_ * MT_ * K16_ * 8 * 128];    // 77.3 MB
__device__ uint32_t g_Bm[B_ * W_ * K16_ * 32 * 128];   // 26.2 MB
__device__ float g_rowsum[B_ * W_ * MROWS_];
__device__ float g_sup_inv[B_ * W_ * C_];
__device__ float g_proto[B_ * W_ * C_];
__device__ float g_pn[B_ * W_ * C_];
__device__ float g_qn[B_ * Q_ * C_];
__device__ float g_qd_inv[B_ * MROWS_];                // [b][q*100+p]

__device__ __forceinline__ float warpSum(float v) {
    #pragma unroll
    for (int o = 16; o; o >>= 1) v += __shfl_xor_sync(0xffffffffu, v, o);
    return v;
}

// fp16-accumulate HMMA
__device__ __forceinline__ void mma16h(uint32_t* d, uint4 a, uint32_t b0, uint32_t b1) {
    asm volatile(
        "mma.sync.aligned.m16n8k16.row.col.f16.f16.f16.f16 "
        "{%0,%1}, {%2,%3,%4,%5}, {%6,%7}, {%0,%1};"
        : "+r"(d[0]), "+r"(d[1])
        : "r"(a.x), "r"(a.y), "r"(a.z), "r"(a.w), "r"(b0), "r"(b1));
}

__device__ __forceinline__ void mma_block(uint32_t dh[2][4][2],
                                          uint4 a0, uint4 a1,
                                          uint4 b0, uint4 b1) {
    mma16h(dh[0][0], a0, b0.x, b0.y);  mma16h(dh[0][1], a0, b0.z, b0.w);
    mma16h(dh[0][2], a0, b1.x, b1.y);  mma16h(dh[0][3], a0, b1.z, b1.w);
    mma16h(dh[1][0], a1, b0.x, b0.y);  mma16h(dh[1][1], a1, b0.z, b0.w);
    mma16h(dh[1][2], a1, b1.x, b1.y);  mma16h(dh[1][3], a1, b1.z, b1.w);
}

__device__ __forceinline__ void ins5(float (&t)[5], float v) {
    if (v > t[0]) {
        t[0] = v;
        if (t[0] > t[1]) { float x = t[1]; t[1] = t[0]; t[0] = x;
            if (t[1] > t[2]) { x = t[2]; t[2] = t[1]; t[1] = x;
                if (t[2] > t[3]) { x = t[3]; t[3] = t[2]; t[2] = x;
                    if (t[3] > t[4]) { x = t[4]; t[4] = t[3]; t[3] = x; } } } }
    }
}

// fp16 running top-5 insert (ascending t[0] <= ... <= t[4]); lossless for
// fp16 candidates — ordering in half precision is exact for half values.
__device__ __forceinline__ void ins5h(__half (&t)[5], __half v) {
    if (__hgt(v, t[0])) {
        t[0] = v;
        if (__hgt(t[0], t[1])) { __half x = t[1]; t[1] = t[0]; t[0] = x;
            if (__hgt(t[1], t[2])) { x = t[2]; t[2] = t[1]; t[1] = x;
                if (__hgt(t[2], t[3])) { x = t[3]; t[3] = t[2]; t[2] = x;
                    if (__hgt(t[3], t[4])) { x = t[4]; t[4] = t[3]; t[3] = x; } } } }
    }
}

__device__ __forceinline__ uint32_t pack_h2(float v0, float v1) {
    __half2 h = __floats2half2_rn(v0, v1);   // .x (low) = v0
    return *(uint32_t*)&h;
}

// ---------------------------------------------------------------------------
// Kernel 1: per-(bw,c) support sums. One warp per (bw,c). grid=3200, block=256.
// ---------------------------------------------------------------------------
__global__ void prep_shot_sums(const float* __restrict__ xs) {
    int gw = blockIdx.x * 8 + (threadIdx.x >> 5);
    int lane = threadIdx.x & 31;
    int bw = gw / C_;
    int c = gw - bw * C_;
    const float* base = xs + (size_t)bw * (S_ * C_ * HW_);
    float ss = 0.f, sm = 0.f;
    for (int j = lane; j < S_ * HW_; j += 32) {
        int s = j / HW_;
        int p = j - s * HW_;
        float v = base[((size_t)s * C_ + c) * HW_ + p];
        ss += v * v;
        sm += v;
    }
    ss = warpSum(ss);
    sm = warpSum(sm);
    if (lane == 0) {
        g_sup_inv[bw * C_ + c] = rsqrtf(ss);
        g_proto[bw * C_ + c] = sm * (1.0f / (S_ * HW_));
    }
}

// Kernel: normalize prototypes. grid=40, block=256.
__global__ void prep_proto_norm() {
    int bw = blockIdx.x;
    int tid = threadIdx.x;
    float local = 0.f;
    for (int c = tid; c < C_; c += 256) {
        float v = g_proto[bw * C_ + c];
        local += v * v;
    }
    local = warpSum(local);
    __shared__ float part[8];
    if ((tid & 31) == 0) part[tid >> 5] = local;
    __syncthreads();
    __shared__ float sinv;
    if (tid == 0) {
        float t = 0.f;
        #pragma unroll
        for (int k = 0; k < 8; k++) t += part[k];
        sinv = rsqrtf(t);
    }
    __syncthreads();
    for (int c = tid; c < C_; c += 256)
        g_pn[bw * C_ + c] = g_proto[bw * C_ + c] * sinv;
}

// ---------------------------------------------------------------------------
// Kernel 2: pack A SINGLE PASS (unscaled fp16 fragments) + query stats
// (qn, qd_inv). grid = B*Q = 600, block = 256. One sweep of x_query.
// ---------------------------------------------------------------------------
#define CCH 64
__global__ void __launch_bounds__(256) packA(const float* __restrict__ xq) {
    int bq = blockIdx.x;
    int b = bq / Q_;
    int q = bq - b * Q_;
    int tid = threadIdx.x;
    const float* src = xq + (size_t)bq * (C_ * HW_);

    __shared__ float s_t[CCH][101];
    __shared__ float csum[C_];
    __shared__ float persq[HW_];
    __shared__ float part[8];
    __shared__ float sinv;

    if (tid < HW_) persq[tid] = 0.f;
    __syncthreads();

    for (int cc0 = 0; cc0 < C_; cc0 += CCH) {
        for (int idx = tid; idx < CCH * HW_; idx += 256) {
            int cc = idx / HW_;
            int p = idx - cc * HW_;
            s_t[cc][p] = src[(size_t)(cc0 + cc) * HW_ + p];
        }
        __syncthreads();

        int wid = tid >> 5, lane = tid & 31;
        for (int cc = wid; cc < CCH; cc += 8) {
            float sm = 0.f;
            #pragma unroll
            for (int pp = lane; pp < HW_; pp += 32) sm += s_t[cc][pp];
            sm = warpSum(sm);
            if (lane == 0) csum[cc0 + cc] = sm;
        }
        if (tid < HW_) {
            float acc = 0.f;
            #pragma unroll 8
            for (int cc = 0; cc < CCH; cc++) {
                float v = s_t[cc][tid];
                acc += v * v;
            }
            persq[tid] += acc;
        }
        for (int idx = tid; idx < (CCH / 2) * HW_; idx += 256) {
            int cc2 = idx & 31;
            int p = idx >> 5;
            int c = cc0 + cc2 * 2;        // even channel of the pair
            int k16 = c >> 4;
            int c16 = c & 15;             // even
            int r = q * HW_ + p;
            int mt = r >> 7;
            int rl = r & 127;
            int mg = rl >> 4;
            int rr = rl & 15;
            int tig = (c16 & 7) >> 1;
            int reg = (rr >> 3) | ((c16 >> 3) << 1);
            int lane2 = ((rr & 7) << 2) | tig;
            size_t tile = ((size_t)(b * MT_ + mt) * K16_ + k16) * 8 + mg;
            g_A[tile * 128 + lane2 * 4 + reg] = pack_h2(s_t[cc2 * 2][p], s_t[cc2 * 2 + 1][p]);
        }
        __syncthreads();
    }

    if (tid < HW_)
        g_qd_inv[(size_t)b * MROWS_ + q * HW_ + tid] = rsqrtf(persq[tid]);

    float local = 0.f;
    for (int c = tid; c < C_; c += 256) {
        float m = csum[c] * (1.0f / HW_);
        local += m * m;
    }
    local = warpSum(local);
    if ((tid & 31) == 0) part[tid >> 5] = local;
    __syncthreads();
    if (tid == 0) {
        float t = 0.f;
        #pragma unroll
        for (int k = 0; k < 8; k++) t += part[k];
        sinv = rsqrtf(t);
    }
    __syncthreads();
    for (int c = tid; c < C_; c += 256)
        g_qn[bq * C_ + c] = csum[c] * (1.0f / HW_) * sinv;
}

// ---------------------------------------------------------------------------
// Kernel 3: pack B (support descriptors, scaled, fp16, fragment order).
// grid = B*W*S = 200, block = 256.
// ---------------------------------------------------------------------------
__global__ void __launch_bounds__(256) packB(const float* __restrict__ xs) {
    int bws = blockIdx.x;
    int s = bws % S_;
    int bw = bws / S_;
    int tid = threadIdx.x;
    const float* src = xs + (size_t)(bw * S_ + s) * (C_ * HW_);

    __shared__ float s_t[CCH][101];

    for (int cc0 = 0; cc0 < C_; cc0 += CCH) {
        __syncthreads();
        for (int idx = tid; idx < CCH * HW_; idx += 256) {
            int cc = idx / HW_;
            int p = idx - cc * HW_;
            s_t[cc][p] = src[(size_t)(cc0 + cc) * HW_ + p];
        }
        __syncthreads();
        for (int idx = tid; idx < (CCH / 2) * HW_; idx += 256) {
            int cc2 = idx & 31;
            int p = idx >> 5;
            int c = cc0 + cc2 * 2;
            int k16 = c >> 4;
            int c16 = c & 15;
            int d = s * HW_ + p;          // 0..499
            int n16 = d >> 4;
            int nsub = (d >> 3) & 1;
            int nl = d & 7;
            int tig = (c16 & 7) >> 1;
            int reg = c16 >> 3;
            int lane = (nl << 2) | tig;
            float v0 = s_t[cc2 * 2][p] * g_sup_inv[bw * C_ + c];
            float v1 = s_t[cc2 * 2 + 1][p] * g_sup_inv[bw * C_ + c + 1];
            size_t tile = ((size_t)bw * K16_ + k16) * 32 + n16;
            g_Bm[tile * 128 + lane * 4 + nsub * 2 + reg] = pack_h2(v0, v1);
        }
    }
}

// ---------------------------------------------------------------------------
// Kernel 4: mma.sync fp16 GEMM (fp16 acc across all K), fp16 top-5 regs,
// pointer-increment addressing, 4 CTAs/SM (reg cap 64). grid=(59,40).
// 8 warps: 4(M) x 2(N). CTA tile M=128, N=512 in 8 chunks of 64, K=640.
// ---------------------------------------------------------------------------
__global__ void __launch_bounds__(256, 4) gemm_topk() {
    int mt = blockIdx.x;
    int bw = blockIdx.y;
    int b = bw / W_;
    int tid = threadIdx.x;
    int lane = tid & 31;
    int wid = tid >> 5;
    int wm = wid & 3;
    int wn = wid >> 2;

    const uint4* Ab = (const uint4*)g_A + (size_t)(b * MT_ + mt) * (K16_ * 8 * 32)
                      + ((wm * 2) << 5) + lane;
    const uint4* Bb = (const uint4*)g_Bm + (size_t)bw * (K16_ * 32 * 32) + lane;

    const __half NEGINF = __ushort_as_half(0xFC00u);   // -inf
    __half t5[4][5];
    #pragma unroll
    for (int i = 0; i < 4; i++)
        #pragma unroll
        for (int s = 0; s < 5; s++) t5[i][s] = NEGINF;

    #pragma unroll 1
    for (int nc = 0; nc < 8; nc++) {
        uint32_t dh[2][4][2];
        #pragma unroll
        for (int i = 0; i < 2; i++)
            #pragma unroll
            for (int j = 0; j < 4; j++) { dh[i][j][0] = 0u; dh[i][j][1] = 0u; }

        int nb0 = nc * 4 + wn * 2;        // pair-tile index base (2 per warp)
        const uint4* ap = Ab;
        const uint4* bp = Bb + (nb0 << 5);

        #pragma unroll 2
        for (int k = 0; k < K16_; k++) {
            uint4 a0 = ap[0];
            uint4 a1 = ap[32];
            uint4 b0 = bp[0];
            uint4 b1 = bp[32];
            ap += 256;       // next k16: 8 tiles * 32 uint4
            bp += 1024;      // next k16: 32 tiles * 32 uint4
            mma_block(dh, a0, a1, b0, b1);
        }

        // fold this 64-col chunk into per-thread fp16 top-5 (rows: i*2+h)
        int cbase = nc * 64 + wn * 32 + (lane & 3) * 2;
        #pragma unroll
        for (int i = 0; i < 2; i++)
            #pragma unroll
            for (int h = 0; h < 2; h++)
                #pragma unroll
                for (int j = 0; j < 4; j++) {
                    __half2 f = *(__half2*)&dh[i][j][h];
                    int c = cbase + j * 8;
                    if (c < 500) ins5h(t5[i * 2 + h], f.x);
                    if (c + 1 < 500) ins5h(t5[i * 2 + h], f.y);
                }
    }

    // merge per-row top-5 candidates via smem (8 owners x 5 per row)
    __shared__ float s5[128][42];
    int owner = wn * 4 + (lane & 3);   // 0..7
    #pragma unroll
    for (int i = 0; i < 2; i++)
        #pragma unroll
        for (int h = 0; h < 2; h++) {
            int rl = wm * 32 + i * 16 + h * 8 + (lane >> 2);
            #pragma unroll
            for (int s = 0; s < 5; s++)
                s5[rl][owner * 5 + s] = __half2float(t5[i * 2 + h][s]);
        }
    __syncthreads();

    if (tid < 128) {
        float t[5] = {-1e30f, -1e30f, -1e30f, -1e30f, -1e30f};
        #pragma unroll
        for (int s = 0; s < 40; s++) ins5(t, s5[tid][s]);
        int r = mt * 128 + tid;
        if (r < MROWS_) {
            float qi = g_qd_inv[(size_t)b * MROWS_ + r];
            g_rowsum[(size_t)bw * MROWS_ + r] =
                (t[0] + t[1] + t[2] + t[3] + t[4]) * qi;
        }
    }
}

// ---------------------------------------------------------------------------
// Kernel 5: finalize. grid = B*Q*W = 3000, block = 128.
// ---------------------------------------------------------------------------
__global__ void finalize(const float* __restrict__ r_cos, const float* __restrict__ r_dn4,
                         float* __restrict__ out) {
    int idx = blockIdx.x;
    int w = idx % W_;
    int q = (idx / W_) % Q_;
    int b = idx / (W_ * Q_);
    int tid = threadIdx.x;
    int bw = b * W_ + w;
    int bq = b * Q_ + q;

    float cosd = 0.f;
    for (int c = tid; c < C_; c += 128)
        cosd += g_qn[bq * C_ + c] * g_pn[bw * C_ + c];
    float dn4 = 0.f;
    if (tid < HW_)
        dn4 = g_rowsum[(size_t)bw * MROWS_ + q * HW_ + tid];

    cosd = warpSum(cosd);
    dn4 = warpSum(dn4);
    __shared__ float pc[4], pd[4];
    if ((tid & 31) == 0) { pc[tid >> 5] = cosd; pd[tid >> 5] = dn4; }
    __syncthreads();
    if (tid == 0) {
        float c2 = pc[0] + pc[1] + pc[2] + pc[3];
        float a = pd[0] + pd[1] + pd[2] + pd[3];
        out[idx] = r_cos[0] * c2 + r_dn4[0] * (a * (1.0f / NK_));
    }
}

// ---------------------------------------------------------------------------
// gemm_topk stays 4th launch (ncu capture window).
// ---------------------------------------------------------------------------
extern "C" void kernel_launch(void* const* d_in, const int* in_sizes, int n_in,
                              void* d_out, int out_size) {
    const float* x_shot  = (const float*)d_in[0];
    const float* x_query = (const float*)d_in[1];
    const float* r_cos   = (const float*)d_in[2];
    const float* r_dn4   = (const float*)d_in[3];
    float* out = (float*)d_out;

    prep_shot_sums<<<3200, 256>>>(x_shot);
    packA<<<B_ * Q_, 256>>>(x_query);
    packB<<<B_ * W_ * S_, 256>>>(x_shot);
    gemm_topk<<<dim3(MT_, B_ * W_), 256>>>();
    prep_proto_norm<<<40, 256>>>();
    finalize<<<B_ * Q_ * W_, 128>>>(r_cos, r_dn4, out);
}